// round 1
// baseline (speedup 1.0000x reference)
#include <cuda_runtime.h>

// Problem constants
#define B_  4
#define S_  2048
#define D_  768
#define H_  12
#define DH_ 64
#define M_  (B_ * S_)   // 8192 rows
// Note: H_*DH_ == D_ == 768, so q/k/v/z scratch are [M_, 768].

// Scratch (allocation-free rule: __device__ globals)
__device__ float g_q[(size_t)M_ * D_];
__device__ float g_k[(size_t)M_ * D_];
__device__ float g_v[(size_t)M_ * D_];
__device__ float g_z[(size_t)M_ * D_];

// ---------------------------------------------------------------------------
// Kernel 1: fused QKV projection.
// C[m, (t,h,e)] = sum_d X[m,d] * W_t[h,d,e] + b_t[h,e]
// Block tile 64(M) x 64(N); N-tile == exactly one (tensor, head) pair.
// 256 threads, 4x4 micro-tile per thread, BK=16.
// ---------------------------------------------------------------------------
__global__ __launch_bounds__(256) void qkv_kernel(
    const float* __restrict__ X,
    const float* __restrict__ Wq, const float* __restrict__ Wk,
    const float* __restrict__ Wv,
    const float* __restrict__ bq, const float* __restrict__ bk,
    const float* __restrict__ bv)
{
    __shared__ float As[16 * 64];   // [k][m] transposed
    __shared__ float Bs[16 * 64];   // [k][n]

    const int nt = blockIdx.x;          // 0..35
    const int m0 = blockIdx.y * 64;
    const int t  = nt / H_;
    const int h  = nt % H_;
    const float* Wp  = (t == 0) ? Wq : (t == 1) ? Wk : Wv;
    const float* bp  = (t == 0) ? bq : (t == 1) ? bk : bv;
    float*       Out = (t == 0) ? g_q : (t == 1) ? g_k : g_v;

    const int tid = threadIdx.x;
    const int tx  = tid & 15;
    const int ty  = tid >> 4;

    // load indices
    const int ar = tid >> 2;             // 0..63 (A row)
    const int ac = (tid & 3) * 4;        // A col quad
    const int bkr = tid >> 4;            // 0..15 (B k row)
    const int bnc = (tid & 15) * 4;      // B n quad

    float acc[4][4] = {};

    const float4* As4 = (const float4*)As;
    const float4* Bs4 = (const float4*)Bs;

    for (int k0 = 0; k0 < D_; k0 += 16) {
        float4 a = *(const float4*)&X[(size_t)(m0 + ar) * D_ + k0 + ac];
        As[(ac + 0) * 64 + ar] = a.x;
        As[(ac + 1) * 64 + ar] = a.y;
        As[(ac + 2) * 64 + ar] = a.z;
        As[(ac + 3) * 64 + ar] = a.w;
        *(float4*)&Bs[bkr * 64 + bnc] =
            *(const float4*)&Wp[(size_t)h * D_ * DH_ + (size_t)(k0 + bkr) * DH_ + bnc];
        __syncthreads();
#pragma unroll
        for (int k = 0; k < 16; k++) {
            float4 av = As4[k * 16 + ty];
            float4 bv4 = Bs4[k * 16 + tx];
            float aa[4] = {av.x, av.y, av.z, av.w};
            float bb[4] = {bv4.x, bv4.y, bv4.z, bv4.w};
#pragma unroll
            for (int i = 0; i < 4; i++)
#pragma unroll
                for (int j = 0; j < 4; j++)
                    acc[i][j] += aa[i] * bb[j];
        }
        __syncthreads();
    }

    const int col = h * 64 + tx * 4;
#pragma unroll
    for (int i = 0; i < 4; i++) {
        const int m = m0 + ty * 4 + i;
        float4 r;
        r.x = acc[i][0] + bp[h * 64 + tx * 4 + 0];
        r.y = acc[i][1] + bp[h * 64 + tx * 4 + 1];
        r.z = acc[i][2] + bp[h * 64 + tx * 4 + 2];
        r.w = acc[i][3] + bp[h * 64 + tx * 4 + 3];
        *(float4*)&Out[(size_t)m * D_ + col] = r;
    }
}

// ---------------------------------------------------------------------------
// Kernel 2: causal flash attention (streaming softmax).
// One CTA per (b, h, q-tile of 64 rows). k/v tiles of 64.
// smem: qs [d][r] (transposed, pre-scaled), kp dual-use (K as [d][c],
// then P as [r][c]), vs [c][e]. 3 * 16KB = 48KB static.
// ---------------------------------------------------------------------------
__global__ __launch_bounds__(256) void attn_kernel()
{
    __shared__ float qs[64 * 64];   // [d][r], q pre-scaled by 1/sqrt(dh)
    __shared__ float kp[64 * 64];   // K: [d][c]  -> reused as P: [r][c]
    __shared__ float vs[64 * 64];   // [c][e]

    const int qt = gridDim.x - 1 - blockIdx.x;  // launch big-work tiles first
    const int bh = blockIdx.y;
    const int b  = bh / H_;
    const int h  = bh % H_;
    const int q0 = qt * 64;

    const int tid = threadIdx.x;
    const int tx  = tid & 15;
    const int ty  = tid >> 4;

    // Load q tile transposed, scaled by 1/sqrt(64) = 0.125
    {
        const int r = tid & 63;
        const int g = tid >> 6;   // 0..3
        const float* qptr = &g_q[(size_t)(b * S_ + q0 + r) * D_ + h * 64];
#pragma unroll
        for (int u = 0; u < 4; u++) {
            const int e0 = (g + u * 4) * 4;
            float4 qv = *(const float4*)&qptr[e0];
            qs[(e0 + 0) * 64 + r] = qv.x * 0.125f;
            qs[(e0 + 1) * 64 + r] = qv.y * 0.125f;
            qs[(e0 + 2) * 64 + r] = qv.z * 0.125f;
            qs[(e0 + 3) * 64 + r] = qv.w * 0.125f;
        }
    }

    float acc[4][4] = {};
    float mrun[4], lrun[4];
#pragma unroll
    for (int i = 0; i < 4; i++) { mrun[i] = -1e30f; lrun[i] = 0.0f; }

    const float4* qs4 = (const float4*)qs;
    const float4* ks4 = (const float4*)kp;

    for (int kt = 0; kt <= qt; kt++) {
        const int k0 = kt * 64;
        __syncthreads();   // protect kp/vs (prev iter reads done; q load visible)

        // Load K tile transposed, V tile natural
        {
            const int r = tid & 63;
            const int g = tid >> 6;
            const float* kptr = &g_k[(size_t)(b * S_ + k0 + r) * D_ + h * 64];
            const float* vptr = &g_v[(size_t)(b * S_ + k0 + r) * D_ + h * 64];
#pragma unroll
            for (int u = 0; u < 4; u++) {
                const int e0 = (g + u * 4) * 4;
                float4 kv = *(const float4*)&kptr[e0];
                kp[(e0 + 0) * 64 + r] = kv.x;
                kp[(e0 + 1) * 64 + r] = kv.y;
                kp[(e0 + 2) * 64 + r] = kv.z;
                kp[(e0 + 3) * 64 + r] = kv.w;
                *(float4*)&vs[r * 64 + e0] = *(const float4*)&vptr[e0];
            }
        }
        __syncthreads();

        // Scores: s[i][j] = sum_d qs[d][ty*4+i] * ks[d][tx*4+j]
        float s[4][4] = {};
#pragma unroll
        for (int d = 0; d < 64; d++) {
            float4 qv = qs4[d * 16 + ty];
            float4 kv = ks4[d * 16 + tx];
            float qa[4] = {qv.x, qv.y, qv.z, qv.w};
            float kb[4] = {kv.x, kv.y, kv.z, kv.w};
#pragma unroll
            for (int i = 0; i < 4; i++)
#pragma unroll
                for (int j = 0; j < 4; j++)
                    s[i][j] += qa[i] * kb[j];
        }

        // Causal mask (only diagonal tile needs it)
        if (kt == qt) {
#pragma unroll
            for (int i = 0; i < 4; i++)
#pragma unroll
                for (int j = 0; j < 4; j++)
                    if (k0 + tx * 4 + j > q0 + ty * 4 + i) s[i][j] = -1e30f;
        }

        // Streaming softmax update (row group = 16 consecutive lanes)
        float p[4][4];
#pragma unroll
        for (int i = 0; i < 4; i++) {
            float mloc = fmaxf(fmaxf(s[i][0], s[i][1]), fmaxf(s[i][2], s[i][3]));
#pragma unroll
            for (int w = 1; w < 16; w <<= 1)
                mloc = fmaxf(mloc, __shfl_xor_sync(0xffffffffu, mloc, w));
            const float mnew = fmaxf(mrun[i], mloc);
            const float alpha = __expf(mrun[i] - mnew);
            mrun[i] = mnew;
            float lloc = 0.0f;
#pragma unroll
            for (int j = 0; j < 4; j++) {
                p[i][j] = __expf(s[i][j] - mnew);
                lloc += p[i][j];
            }
#pragma unroll
            for (int w = 1; w < 16; w <<= 1)
                lloc += __shfl_xor_sync(0xffffffffu, lloc, w);
            lrun[i] = lrun[i] * alpha + lloc;
#pragma unroll
            for (int j = 0; j < 4; j++) acc[i][j] *= alpha;
        }

        __syncthreads();   // all K reads done before P overwrites kp

        // Write P as [r][c] into kp (conflict-free float4 stores)
#pragma unroll
        for (int i = 0; i < 4; i++) {
            float4 pv = make_float4(p[i][0], p[i][1], p[i][2], p[i][3]);
            *(float4*)&kp[(ty * 4 + i) * 64 + tx * 4] = pv;
        }
        __syncthreads();

        // PV: acc[i][j] += sum_c P[ty*4+i][c] * V[c][tx*4+j]
#pragma unroll
        for (int c = 0; c < 64; c++) {
            float4 vv = *(const float4*)&vs[c * 64 + tx * 4];
#pragma unroll
            for (int i = 0; i < 4; i++) {
                const float pc = kp[(ty * 4 + i) * 64 + c];   // broadcast
                acc[i][0] += pc * vv.x;
                acc[i][1] += pc * vv.y;
                acc[i][2] += pc * vv.z;
                acc[i][3] += pc * vv.w;
            }
        }
    }

    // Epilogue: z[b, q0+r, h, e] = acc / l
#pragma unroll
    for (int i = 0; i < 4; i++) {
        const float inv = 1.0f / lrun[i];
        float4 o = make_float4(acc[i][0] * inv, acc[i][1] * inv,
                               acc[i][2] * inv, acc[i][3] * inv);
        *(float4*)&g_z[(size_t)(b * S_ + q0 + ty * 4 + i) * D_ + h * 64 + tx * 4] = o;
    }
}

// ---------------------------------------------------------------------------
// Kernel 3: output projection.
// out[m,d] = sum_{he} z[m,he] * W_O[he,d] + b_O[d]
// W_O [H, Dh, D] flattened row-major is exactly [768, 768] matching z cols.
// ---------------------------------------------------------------------------
__global__ __launch_bounds__(256) void out_kernel(
    const float* __restrict__ Wo, const float* __restrict__ bo,
    float* __restrict__ Out)
{
    __shared__ float As[16 * 64];
    __shared__ float Bs[16 * 64];

    const int n0 = blockIdx.x * 64;
    const int m0 = blockIdx.y * 64;

    const int tid = threadIdx.x;
    const int tx  = tid & 15;
    const int ty  = tid >> 4;

    const int ar  = tid >> 2;
    const int ac  = (tid & 3) * 4;
    const int bkr = tid >> 4;
    const int bnc = (tid & 15) * 4;

    float acc[4][4] = {};
    const float4* As4 = (const float4*)As;
    const float4* Bs4 = (const float4*)Bs;

    for (int k0 = 0; k0 < D_; k0 += 16) {
        float4 a = *(const float4*)&g_z[(size_t)(m0 + ar) * D_ + k0 + ac];
        As[(ac + 0) * 64 + ar] = a.x;
        As[(ac + 1) * 64 + ar] = a.y;
        As[(ac + 2) * 64 + ar] = a.z;
        As[(ac + 3) * 64 + ar] = a.w;
        *(float4*)&Bs[bkr * 64 + bnc] =
            *(const float4*)&Wo[(size_t)(k0 + bkr) * D_ + n0 + bnc];
        __syncthreads();
#pragma unroll
        for (int k = 0; k < 16; k++) {
            float4 av = As4[k * 16 + ty];
            float4 bv4 = Bs4[k * 16 + tx];
            float aa[4] = {av.x, av.y, av.z, av.w};
            float bb[4] = {bv4.x, bv4.y, bv4.z, bv4.w};
#pragma unroll
            for (int i = 0; i < 4; i++)
#pragma unroll
                for (int j = 0; j < 4; j++)
                    acc[i][j] += aa[i] * bb[j];
        }
        __syncthreads();
    }

#pragma unroll
    for (int i = 0; i < 4; i++) {
        const int m = m0 + ty * 4 + i;
        float4 r;
        r.x = acc[i][0] + bo[n0 + tx * 4 + 0];
        r.y = acc[i][1] + bo[n0 + tx * 4 + 1];
        r.z = acc[i][2] + bo[n0 + tx * 4 + 2];
        r.w = acc[i][3] + bo[n0 + tx * 4 + 3];
        *(float4*)&Out[(size_t)m * D_ + n0 + tx * 4] = r;
    }
}

// ---------------------------------------------------------------------------
// Launch. Inputs (metadata order): residual, W_Q, W_K, W_V, W_O,
//                                  b_Q, b_K, b_V, b_O
// ---------------------------------------------------------------------------
extern "C" void kernel_launch(void* const* d_in, const int* in_sizes, int n_in,
                              void* d_out, int out_size)
{
    const float* X  = (const float*)d_in[0];
    const float* Wq = (const float*)d_in[1];
    const float* Wk = (const float*)d_in[2];
    const float* Wv = (const float*)d_in[3];
    const float* Wo = (const float*)d_in[4];
    const float* bq = (const float*)d_in[5];
    const float* bk = (const float*)d_in[6];
    const float* bv = (const float*)d_in[7];
    const float* bo = (const float*)d_in[8];
    float* out = (float*)d_out;

    qkv_kernel<<<dim3(3 * H_, M_ / 64), 256>>>(X, Wq, Wk, Wv, bq, bk, bv);
    attn_kernel<<<dim3(S_ / 64, B_ * H_), 256>>>();
    out_kernel<<<dim3(D_ / 64, M_ / 64), 256>>>(Wo, bo, out);
}

// round 2
// speedup vs baseline: 1.1548x; 1.1548x over previous
#include <cuda_runtime.h>

#define B_  4
#define S_  2048
#define D_  768
#define H_  12
#define M_  (B_ * S_)   // 8192

// Scratch (allocation-free rule)
__device__ float g_q[(size_t)M_ * D_];
__device__ float g_k[(size_t)M_ * D_];
__device__ float g_v[(size_t)M_ * D_];
__device__ float g_z[(size_t)M_ * D_];

// ---------------------------------------------------------------------------
// Kernel 1: fused QKV projection. C = X[8192x768] * W[768x2304] (+bias)
// 128x128 block tile, BK=16, 256 threads, 8x8 micro-tile.
// As stored transposed [k][m] with stride 132 (pad) for conflict-free reads.
// ---------------------------------------------------------------------------
__global__ __launch_bounds__(256, 2) void qkv_kernel(
    const float* __restrict__ X,
    const float* __restrict__ Wq, const float* __restrict__ Wk,
    const float* __restrict__ Wv,
    const float* __restrict__ bq, const float* __restrict__ bk,
    const float* __restrict__ bv)
{
    __shared__ float As[16 * 132];
    __shared__ float Bs[16 * 128];

    const int n0  = blockIdx.x * 128;        // global fused col
    const int m0  = blockIdx.y * 128;
    const int t   = n0 / D_;                 // tensor select (128 | 768)
    const int nn0 = n0 - t * D_;             // col within tensor [0,768)
    const float* Wp  = (t == 0) ? Wq : (t == 1) ? Wk : Wv;
    const float* bp  = (t == 0) ? bq : (t == 1) ? bk : bv;
    float*       Out = (t == 0) ? g_q : (t == 1) ? g_k : g_v;

    const int tid = threadIdx.x;
    const int tx  = tid & 15;
    const int ty  = tid >> 4;

    // A load: thread -> row ar, k-range [ak, ak+8)
    const int ar = tid >> 1;
    const int ak = (tid & 1) * 8;
    // B load: thread -> k-row bkr, n-range [bn, bn+8)
    const int bkr = tid >> 4;
    const int bn  = (tid & 15) * 8;
    const int cc0 = nn0 + bn;                // within-tensor col of load
    const int h0  = cc0 >> 6;
    const int e0  = cc0 & 63;                // multiple of 8 -> one head per quad pair

    float acc[8][8] = {};
    const float4* As4 = (const float4*)As;
    const float4* Bs4 = (const float4*)Bs;

    for (int k0 = 0; k0 < D_; k0 += 16) {
        float4 a0 = *(const float4*)&X[(size_t)(m0 + ar) * D_ + k0 + ak];
        float4 a1 = *(const float4*)&X[(size_t)(m0 + ar) * D_ + k0 + ak + 4];
        As[(ak + 0) * 132 + ar] = a0.x;
        As[(ak + 1) * 132 + ar] = a0.y;
        As[(ak + 2) * 132 + ar] = a0.z;
        As[(ak + 3) * 132 + ar] = a0.w;
        As[(ak + 4) * 132 + ar] = a1.x;
        As[(ak + 5) * 132 + ar] = a1.y;
        As[(ak + 6) * 132 + ar] = a1.z;
        As[(ak + 7) * 132 + ar] = a1.w;
        const float* wrow = &Wp[(size_t)h0 * D_ * 64 + (size_t)(k0 + bkr) * 64 + e0];
        *(float4*)&Bs[bkr * 128 + bn]     = *(const float4*)&wrow[0];
        *(float4*)&Bs[bkr * 128 + bn + 4] = *(const float4*)&wrow[4];
        __syncthreads();
#pragma unroll
        for (int k = 0; k < 16; k++) {
            float4 a0v = As4[k * 33 + ty * 2];
            float4 a1v = As4[k * 33 + ty * 2 + 1];
            float4 b0v = Bs4[k * 32 + tx * 2];
            float4 b1v = Bs4[k * 32 + tx * 2 + 1];
            float aa[8] = {a0v.x, a0v.y, a0v.z, a0v.w, a1v.x, a1v.y, a1v.z, a1v.w};
            float bb[8] = {b0v.x, b0v.y, b0v.z, b0v.w, b1v.x, b1v.y, b1v.z, b1v.w};
#pragma unroll
            for (int i = 0; i < 8; i++)
#pragma unroll
                for (int j = 0; j < 8; j++)
                    acc[i][j] += aa[i] * bb[j];
        }
        __syncthreads();
    }

    const int ccw = nn0 + tx * 8;            // within-tensor output col
#pragma unroll
    for (int i = 0; i < 8; i++) {
        const int m = m0 + ty * 8 + i;
        float4 r0, r1;
        r0.x = acc[i][0] + bp[ccw + 0];
        r0.y = acc[i][1] + bp[ccw + 1];
        r0.z = acc[i][2] + bp[ccw + 2];
        r0.w = acc[i][3] + bp[ccw + 3];
        r1.x = acc[i][4] + bp[ccw + 4];
        r1.y = acc[i][5] + bp[ccw + 5];
        r1.z = acc[i][6] + bp[ccw + 6];
        r1.w = acc[i][7] + bp[ccw + 7];
        *(float4*)&Out[(size_t)m * D_ + ccw]     = r0;
        *(float4*)&Out[(size_t)m * D_ + ccw + 4] = r1;
    }
}

// ---------------------------------------------------------------------------
// Kernel 2: causal flash attention.
// CTA = (b, h, 128-row q tile); k/v tiles of 64. 256 threads.
// Score micro-tile 8x4 (rows ty*8+i, cols tx*4+j); output acc 8x4.
// smem (dynamic, 100KB): qs[64][132] (q^T, pre-scaled), ks[64][68] (K^T),
// vs[64][68], ps[64][132] (P^T as [c][r]).
// ---------------------------------------------------------------------------
__global__ __launch_bounds__(256, 2) void attn_kernel()
{
    extern __shared__ float sm[];
    float* qs = sm;                   // 64 * 132
    float* ks = qs + 64 * 132;        // 64 * 68
    float* vs = ks + 64 * 68;         // 64 * 68
    float* ps = vs + 64 * 68;         // 64 * 132

    const int qt = gridDim.x - 1 - blockIdx.x;  // heavy tiles first
    const int bh = blockIdx.y;
    const int b  = bh / H_;
    const int h  = bh % H_;
    const int q0 = qt * 128;

    const int tid = threadIdx.x;
    const int tx  = tid & 15;
    const int ty  = tid >> 4;

    // Load q tile transposed + scaled (1/sqrt(64) = 0.125)
    {
        const int r    = tid & 127;
        const int half = tid >> 7;             // 0/1 -> d 0..31 / 32..63
        const float* qptr = &g_q[(size_t)(b * S_ + q0 + r) * D_ + h * 64 + half * 32];
#pragma unroll
        for (int u = 0; u < 8; u++) {
            const int d = half * 32 + u * 4;
            float4 qv = *(const float4*)&qptr[u * 4];
            qs[(d + 0) * 132 + r] = qv.x * 0.125f;
            qs[(d + 1) * 132 + r] = qv.y * 0.125f;
            qs[(d + 2) * 132 + r] = qv.z * 0.125f;
            qs[(d + 3) * 132 + r] = qv.w * 0.125f;
        }
    }

    float acc[8][4] = {};
    float mrun[8], lrun[8];
#pragma unroll
    for (int i = 0; i < 8; i++) { mrun[i] = -1e30f; lrun[i] = 0.0f; }

    const float4* qs4 = (const float4*)qs;
    const float4* ks4 = (const float4*)ks;
    const float4* ps4 = (const float4*)ps;
    const float4* vs4 = (const float4*)vs;

    const int ntiles = 2 * qt + 2;
    for (int kt = 0; kt < ntiles; kt++) {
        const int k0 = kt * 64;
        __syncthreads();   // prev iter PV reads of ks/vs/ps done; qs visible (1st)

        // Load K^T into ks[d][c], V into vs[c][e]
        {
            const int c = tid & 63;
            const int g = tid >> 6;            // 0..3
            const float* kptr = &g_k[(size_t)(b * S_ + k0 + c) * D_ + h * 64 + g * 16];
            const float* vptr = &g_v[(size_t)(b * S_ + k0 + c) * D_ + h * 64 + g * 16];
#pragma unroll
            for (int u = 0; u < 4; u++) {
                const int d = g * 16 + u * 4;
                float4 kv = *(const float4*)&kptr[u * 4];
                ks[(d + 0) * 68 + c] = kv.x;
                ks[(d + 1) * 68 + c] = kv.y;
                ks[(d + 2) * 68 + c] = kv.z;
                ks[(d + 3) * 68 + c] = kv.w;
                *(float4*)&vs[c * 68 + d] = *(const float4*)&vptr[u * 4];
            }
        }
        __syncthreads();

        // Scores s[i][j] = sum_d qs[d][ty*8+i] * ks[d][tx*4+j]
        float s[8][4] = {};
#pragma unroll
        for (int d = 0; d < 64; d++) {
            float4 q0v = qs4[d * 33 + ty * 2];
            float4 q1v = qs4[d * 33 + ty * 2 + 1];
            float4 kv  = ks4[d * 17 + tx];
            float qa[8] = {q0v.x, q0v.y, q0v.z, q0v.w, q1v.x, q1v.y, q1v.z, q1v.w};
            float kb[4] = {kv.x, kv.y, kv.z, kv.w};
#pragma unroll
            for (int i = 0; i < 8; i++)
#pragma unroll
                for (int j = 0; j < 4; j++)
                    s[i][j] += qa[i] * kb[j];
        }

        // Causal mask: only the two diagonal tiles need it
        if (kt >= 2 * qt) {
#pragma unroll
            for (int i = 0; i < 8; i++)
#pragma unroll
                for (int j = 0; j < 4; j++)
                    if (k0 + tx * 4 + j > q0 + ty * 8 + i) s[i][j] = -1e30f;
        }

        // Streaming softmax (row group = 16 consecutive lanes)
        float p[8][4];
#pragma unroll
        for (int i = 0; i < 8; i++) {
            float mloc = fmaxf(fmaxf(s[i][0], s[i][1]), fmaxf(s[i][2], s[i][3]));
#pragma unroll
            for (int w = 1; w < 16; w <<= 1)
                mloc = fmaxf(mloc, __shfl_xor_sync(0xffffffffu, mloc, w));
            const float mnew  = fmaxf(mrun[i], mloc);
            const float alpha = __expf(mrun[i] - mnew);
            mrun[i] = mnew;
            float lloc = 0.0f;
#pragma unroll
            for (int j = 0; j < 4; j++) {
                p[i][j] = __expf(s[i][j] - mnew);
                lloc += p[i][j];
            }
#pragma unroll
            for (int w = 1; w < 16; w <<= 1)
                lloc += __shfl_xor_sync(0xffffffffu, lloc, w);
            lrun[i] = lrun[i] * alpha + lloc;
#pragma unroll
            for (int j = 0; j < 4; j++) acc[i][j] *= alpha;
        }

        // Write P^T into ps[c][r] (float4 over rows)
#pragma unroll
        for (int j = 0; j < 4; j++) {
            const int c = tx * 4 + j;
            float4 p0 = make_float4(p[0][j], p[1][j], p[2][j], p[3][j]);
            float4 p1 = make_float4(p[4][j], p[5][j], p[6][j], p[7][j]);
            *(float4*)&ps[c * 132 + ty * 8]     = p0;
            *(float4*)&ps[c * 132 + ty * 8 + 4] = p1;
        }
        __syncthreads();

        // PV: acc[i][j] += sum_c ps[c][ty*8+i] * vs[c][tx*4+j]
#pragma unroll
        for (int c = 0; c < 64; c++) {
            float4 p0v = ps4[c * 33 + ty * 2];
            float4 p1v = ps4[c * 33 + ty * 2 + 1];
            float4 vv  = vs4[c * 17 + tx];
            float pa[8] = {p0v.x, p0v.y, p0v.z, p0v.w, p1v.x, p1v.y, p1v.z, p1v.w};
#pragma unroll
            for (int i = 0; i < 8; i++) {
                acc[i][0] += pa[i] * vv.x;
                acc[i][1] += pa[i] * vv.y;
                acc[i][2] += pa[i] * vv.z;
                acc[i][3] += pa[i] * vv.w;
            }
        }
    }

    // Epilogue: z = acc / l
#pragma unroll
    for (int i = 0; i < 8; i++) {
        const float inv = 1.0f / lrun[i];
        float4 o = make_float4(acc[i][0] * inv, acc[i][1] * inv,
                               acc[i][2] * inv, acc[i][3] * inv);
        *(float4*)&g_z[(size_t)(b * S_ + q0 + ty * 8 + i) * D_ + h * 64 + tx * 4] = o;
    }
}

// ---------------------------------------------------------------------------
// Kernel 3: output projection. out = z[8192x768] * Wo[768x768] + bo
// Same 128x128 / 8x8 structure.
// ---------------------------------------------------------------------------
__global__ __launch_bounds__(256, 2) void out_kernel(
    const float* __restrict__ Wo, const float* __restrict__ bo,
    float* __restrict__ Out)
{
    __shared__ float As[16 * 132];
    __shared__ float Bs[16 * 128];

    const int n0 = blockIdx.x * 128;
    const int m0 = blockIdx.y * 128;

    const int tid = threadIdx.x;
    const int tx  = tid & 15;
    const int ty  = tid >> 4;

    const int ar  = tid >> 1;
    const int ak  = (tid & 1) * 8;
    const int bkr = tid >> 4;
    const int bn  = (tid & 15) * 8;

    float acc[8][8] = {};
    const float4* As4 = (const float4*)As;
    const float4* Bs4 = (const float4*)Bs;

    for (int k0 = 0; k0 < D_; k0 += 16) {
        float4 a0 = *(const float4*)&g_z[(size_t)(m0 + ar) * D_ + k0 + ak];
        float4 a1 = *(const float4*)&g_z[(size_t)(m0 + ar) * D_ + k0 + ak + 4];
        As[(ak + 0) * 132 + ar] = a0.x;
        As[(ak + 1) * 132 + ar] = a0.y;
        As[(ak + 2) * 132 + ar] = a0.z;
        As[(ak + 3) * 132 + ar] = a0.w;
        As[(ak + 4) * 132 + ar] = a1.x;
        As[(ak + 5) * 132 + ar] = a1.y;
        As[(ak + 6) * 132 + ar] = a1.z;
        As[(ak + 7) * 132 + ar] = a1.w;
        const float* wrow = &Wo[(size_t)(k0 + bkr) * D_ + n0 + bn];
        *(float4*)&Bs[bkr * 128 + bn]     = *(const float4*)&wrow[0];
        *(float4*)&Bs[bkr * 128 + bn + 4] = *(const float4*)&wrow[4];
        __syncthreads();
#pragma unroll
        for (int k = 0; k < 16; k++) {
            float4 a0v = As4[k * 33 + ty * 2];
            float4 a1v = As4[k * 33 + ty * 2 + 1];
            float4 b0v = Bs4[k * 32 + tx * 2];
            float4 b1v = Bs4[k * 32 + tx * 2 + 1];
            float aa[8] = {a0v.x, a0v.y, a0v.z, a0v.w, a1v.x, a1v.y, a1v.z, a1v.w};
            float bb[8] = {b0v.x, b0v.y, b0v.z, b0v.w, b1v.x, b1v.y, b1v.z, b1v.w};
#pragma unroll
            for (int i = 0; i < 8; i++)
#pragma unroll
                for (int j = 0; j < 8; j++)
                    acc[i][j] += aa[i] * bb[j];
        }
        __syncthreads();
    }

#pragma unroll
    for (int i = 0; i < 8; i++) {
        const int m = m0 + ty * 8 + i;
        const int c = n0 + tx * 8;
        float4 r0, r1;
        r0.x = acc[i][0] + bo[c + 0];
        r0.y = acc[i][1] + bo[c + 1];
        r0.z = acc[i][2] + bo[c + 2];
        r0.w = acc[i][3] + bo[c + 3];
        r1.x = acc[i][4] + bo[c + 4];
        r1.y = acc[i][5] + bo[c + 5];
        r1.z = acc[i][6] + bo[c + 6];
        r1.w = acc[i][7] + bo[c + 7];
        *(float4*)&Out[(size_t)m * D_ + c]     = r0;
        *(float4*)&Out[(size_t)m * D_ + c + 4] = r1;
    }
}

// ---------------------------------------------------------------------------
// Launch
// ---------------------------------------------------------------------------
extern "C" void kernel_launch(void* const* d_in, const int* in_sizes, int n_in,
                              void* d_out, int out_size)
{
    const float* X  = (const float*)d_in[0];
    const float* Wq = (const float*)d_in[1];
    const float* Wk = (const float*)d_in[2];
    const float* Wv = (const float*)d_in[3];
    const float* Wo = (const float*)d_in[4];
    const float* bq = (const float*)d_in[5];
    const float* bk = (const float*)d_in[6];
    const float* bv = (const float*)d_in[7];
    const float* bo = (const float*)d_in[8];
    float* out = (float*)d_out;

    const int attn_smem = (64 * 132 + 64 * 68 + 64 * 68 + 64 * 132) * 4; // 102400
    static bool attr_set = false;
    if (!attr_set) {
        cudaFuncSetAttribute(attn_kernel,
                             cudaFuncAttributeMaxDynamicSharedMemorySize, attn_smem);
        attr_set = true;
    }

    qkv_kernel<<<dim3(3 * D_ / 128, M_ / 128), 256>>>(X, Wq, Wk, Wv, bq, bk, bv);
    attn_kernel<<<dim3(S_ / 128, B_ * H_), 256, attn_smem>>>();
    out_kernel<<<dim3(D_ / 128, M_ / 128), 256>>>(Wo, bo, out);
}

// round 4
// speedup vs baseline: 1.5502x; 1.3423x over previous
#include <cuda_runtime.h>
#include <cuda_bf16.h>
#include <cstdint>

#define B_  4
#define S_  2048
#define D_  768
#define H_  12
#define M_  (B_ * S_)     // 8192
#define NF_ (3 * D_)      // 2304 fused qkv cols

// ------------------------- device scratch (no allocs) -----------------------
__device__ float          g_qkv[(size_t)M_ * NF_];   // fused q|k|v fp32
__device__ __nv_bfloat16  g_xh [(size_t)M_ * D_];    // residual hi/lo
__device__ __nv_bfloat16  g_xl [(size_t)M_ * D_];
__device__ __nv_bfloat16  g_zh [(size_t)M_ * D_];    // attention out hi/lo
__device__ __nv_bfloat16  g_zl [(size_t)M_ * D_];
__device__ __nv_bfloat16  g_wth[(size_t)NF_ * D_];   // W_{q,k,v}^T  [n][d]
__device__ __nv_bfloat16  g_wtl[(size_t)NF_ * D_];
__device__ __nv_bfloat16  g_woh[(size_t)D_ * D_];    // W_O^T [d_out][he]
__device__ __nv_bfloat16  g_wol[(size_t)D_ * D_];
__device__ float          g_fb [NF_];                // fused qkv bias

// ------------------------------ PTX helpers --------------------------------
__device__ __forceinline__ uint32_t smem_u32(const void* p) {
    uint32_t a;
    asm("{ .reg .u64 t; cvta.to.shared.u64 t, %1; cvt.u32.u64 %0, t; }"
        : "=r"(a) : "l"(p));
    return a;
}
__device__ __forceinline__ void ldsm_x4(uint32_t* r, uint32_t addr) {
    asm volatile("ldmatrix.sync.aligned.m8n8.x4.shared.b16 {%0,%1,%2,%3}, [%4];"
                 : "=r"(r[0]), "=r"(r[1]), "=r"(r[2]), "=r"(r[3]) : "r"(addr));
}
__device__ __forceinline__ void mma16816(float* c, const uint32_t* a,
                                         uint32_t b0, uint32_t b1) {
    asm volatile(
        "mma.sync.aligned.m16n8k16.row.col.f32.bf16.bf16.f32 "
        "{%0,%1,%2,%3}, {%4,%5,%6,%7}, {%8,%9}, {%0,%1,%2,%3};"
        : "+f"(c[0]), "+f"(c[1]), "+f"(c[2]), "+f"(c[3])
        : "r"(a[0]), "r"(a[1]), "r"(a[2]), "r"(a[3]), "r"(b0), "r"(b1));
}

// --------------------------- conversion kernels ----------------------------
__global__ void split_kernel(const float* __restrict__ src,
                             __nv_bfloat16* __restrict__ dh,
                             __nv_bfloat16* __restrict__ dl, int n) {
    int i8 = (blockIdx.x * 256 + threadIdx.x) * 8;
    if (i8 >= n) return;
    float4 v0 = *(const float4*)&src[i8];
    float4 v1 = *(const float4*)&src[i8 + 4];
    float v[8] = {v0.x, v0.y, v0.z, v0.w, v1.x, v1.y, v1.z, v1.w};
    __align__(16) __nv_bfloat16 h[8], l[8];
#pragma unroll
    for (int j = 0; j < 8; j++) {
        h[j] = __float2bfloat16(v[j]);
        l[j] = __float2bfloat16(v[j] - __bfloat162float(h[j]));
    }
    *(uint4*)&dh[i8] = *(uint4*)h;
    *(uint4*)&dl[i8] = *(uint4*)l;
}

// transpose + split a 64x64 tile: dst[base + c0 + c][r0 + r] = src[r0+r][c0+c]
__device__ __forceinline__ void trans_tile(const float* src, int src_ld,
                                           __nv_bfloat16* dh, __nv_bfloat16* dl,
                                           int dst_ld, int r0, int c0, int base) {
    __shared__ float ts[64 * 65];
    const int tid = threadIdx.x;
#pragma unroll
    for (int it = 0; it < 16; it++) {
        int flat = tid + it * 256;
        int i = flat >> 6, c = flat & 63;
        ts[c * 65 + i] = src[(size_t)(r0 + i) * src_ld + c0 + c];
    }
    __syncthreads();
#pragma unroll
    for (int it = 0; it < 8; it++) {
        int flat = tid + it * 256;
        int c = flat >> 5, rj = flat & 31;
        float v0 = ts[c * 65 + rj * 2], v1 = ts[c * 65 + rj * 2 + 1];
        __nv_bfloat16 h0 = __float2bfloat16(v0), h1 = __float2bfloat16(v1);
        __nv_bfloat16 l0 = __float2bfloat16(v0 - __bfloat162float(h0));
        __nv_bfloat16 l1 = __float2bfloat16(v1 - __bfloat162float(h1));
        __nv_bfloat162 hp = {h0, h1}, lp = {l0, l1};
        size_t o = (size_t)(base + c0 + c) * dst_ld + r0 + rj * 2;
        *(uint32_t*)&dh[o] = *(uint32_t*)&hp;
        *(uint32_t*)&dl[o] = *(uint32_t*)&lp;
    }
}

__global__ void trans_qkv_kernel(const float* __restrict__ Wq,
                                 const float* __restrict__ Wk,
                                 const float* __restrict__ Wv) {
    const int by = blockIdx.y;        // 0..35
    const int t = by / H_, h = by % H_;
    const float* src = ((t == 0) ? Wq : (t == 1) ? Wk : Wv) + (size_t)h * D_ * 64;
    trans_tile(src, 64, g_wth, g_wtl, D_, blockIdx.x * 64, 0, t * D_ + h * 64);
}
__global__ void trans_wo_kernel(const float* __restrict__ Wo) {
    trans_tile(Wo, D_, g_woh, g_wol, D_, blockIdx.x * 64, blockIdx.y * 64, 0);
}
__global__ void fuse_bias_kernel(const float* __restrict__ bq,
                                 const float* __restrict__ bk,
                                 const float* __restrict__ bv) {
    int n = blockIdx.x * 256 + threadIdx.x;
    if (n < NF_) g_fb[n] = (n < D_) ? bq[n] : (n < 2 * D_) ? bk[n - D_] : bv[n - 2 * D_];
}

// ------------------------ mma.sync bf16x3 GEMM ------------------------------
// C[128x128] = (Ah+Al)[Mx768] * ((Bh+Bl)[Nx768])^T + bias, dropping Al*Bl.
// 256 thr = 8 warps (2x4); warp tile 64x32; m16n8k16 atoms; BK=32.
// smem tiles [128][40] bf16 (80B row stride -> ldmatrix conflict-free).
__global__ __launch_bounds__(256, 1)
void gemm_mma_kernel(const __nv_bfloat16* __restrict__ Ah,
                     const __nv_bfloat16* __restrict__ Al,
                     const __nv_bfloat16* __restrict__ Bh,
                     const __nv_bfloat16* __restrict__ Bl,
                     float* __restrict__ out, int ld_out,
                     const float* __restrict__ bias) {
    __shared__ __align__(16) __nv_bfloat16 smt[4 * 128 * 40];
    const uint32_t sb = smem_u32(smt);

    const int tid  = threadIdx.x;
    const int wid  = tid >> 5;
    const int lane = tid & 31;
    const int wr   = wid >> 2;          // 0..1
    const int wc   = wid & 3;           // 0..3
    const size_t m0 = blockIdx.y * 128;
    const size_t n0 = blockIdx.x * 128;

    // load mapping: flat = tid + it*256; r = flat>>2, c8 = flat&3
    const int lr  = tid >> 2;
    const int lc8 = tid & 3;

    const __nv_bfloat16* srcs[4] = {Ah, Al, Bh, Bl};
    const size_t rbase[4] = {m0, m0, n0, n0};

    float acc[4][4][4] = {};

    // prologue: load k-tile 0
#pragma unroll
    for (int p = 0; p < 4; p++)
#pragma unroll
        for (int it = 0; it < 2; it++) {
            int r = lr + it * 64;
            uint4 v = *(const uint4*)&srcs[p][(rbase[p] + r) * D_ + lc8 * 8];
            *(uint4*)&smt[p * 5120 + r * 40 + lc8 * 8] = v;
        }
    __syncthreads();

    const int lrow = lane & 15;
    const int lcol = (lane >> 4) * 8;

    for (int kt = 0; kt < 24; kt++) {
        // prefetch next k-tile into registers
        uint4 pref[8];
        if (kt < 23) {
            const int k0n = (kt + 1) * 32;
#pragma unroll
            for (int p = 0; p < 4; p++)
#pragma unroll
                for (int it = 0; it < 2; it++) {
                    int r = lr + it * 64;
                    pref[p * 2 + it] =
                        *(const uint4*)&srcs[p][(rbase[p] + r) * D_ + k0n + lc8 * 8];
                }
        }

        // compute from smem
#pragma unroll
        for (int ks = 0; ks < 2; ks++) {
            const int kb = ks * 16;
            uint32_t aFh[4][4], aFl[4][4], bFh[2][4], bFl[2][4];
#pragma unroll
            for (int mt = 0; mt < 4; mt++) {
                int row = wr * 64 + mt * 16 + lrow;
                ldsm_x4(aFh[mt], sb + (0 * 5120 + row * 40 + kb + lcol) * 2);
                ldsm_x4(aFl[mt], sb + (1 * 5120 + row * 40 + kb + lcol) * 2);
            }
#pragma unroll
            for (int np = 0; np < 2; np++) {
                int row = wc * 32 + np * 16 + lrow;
                ldsm_x4(bFh[np], sb + (2 * 5120 + row * 40 + kb + lcol) * 2);
                ldsm_x4(bFl[np], sb + (3 * 5120 + row * 40 + kb + lcol) * 2);
            }
#pragma unroll
            for (int mt = 0; mt < 4; mt++)
#pragma unroll
                for (int nt = 0; nt < 4; nt++) {
                    const int np = nt >> 1, ni = nt & 1;
                    mma16816(acc[mt][nt], aFh[mt], bFh[np][ni], bFh[np][ni + 2]);
                    mma16816(acc[mt][nt], aFh[mt], bFl[np][ni], bFl[np][ni + 2]);
                    mma16816(acc[mt][nt], aFl[mt], bFh[np][ni], bFh[np][ni + 2]);
                }
        }
        __syncthreads();
        if (kt < 23) {
#pragma unroll
            for (int p = 0; p < 4; p++)
#pragma unroll
                for (int it = 0; it < 2; it++) {
                    int r = lr + it * 64;
                    *(uint4*)&smt[p * 5120 + r * 40 + lc8 * 8] = pref[p * 2 + it];
                }
            __syncthreads();
        }
    }

    // epilogue: direct gmem stores + bias
    const int g = lane >> 2;
    const int cb = (lane & 3) * 2;
#pragma unroll
    for (int mt = 0; mt < 4; mt++)
#pragma unroll
        for (int nt = 0; nt < 4; nt++) {
            const size_t col = n0 + wc * 32 + nt * 8 + cb;
            float2 bv = *(const float2*)&bias[col];
            const size_t r0 = m0 + wr * 64 + mt * 16 + g;
            float2 v0 = {acc[mt][nt][0] + bv.x, acc[mt][nt][1] + bv.y};
            float2 v1 = {acc[mt][nt][2] + bv.x, acc[mt][nt][3] + bv.y};
            *(float2*)&out[r0 * ld_out + col]       = v0;
            *(float2*)&out[(r0 + 8) * ld_out + col] = v1;
        }
}

// ----------------------- fp32 causal flash attention ------------------------
__global__ __launch_bounds__(256, 2) void attn_kernel() {
    extern __shared__ float sm[];
    float* qs = sm;                   // 64 * 132
    float* ks = qs + 64 * 132;        // 64 * 68
    float* vs = ks + 64 * 68;         // 64 * 68
    float* ps = vs + 64 * 68;         // 64 * 132

    const int qt = gridDim.x - 1 - blockIdx.x;
    const int bh = blockIdx.y;
    const int b = bh / H_, h = bh % H_;
    const int q0 = qt * 128;
    const int tid = threadIdx.x;
    const int tx = tid & 15, ty = tid >> 4;

    {
        const int r = tid & 127, half = tid >> 7;
        const float* qp = &g_qkv[(size_t)(b * S_ + q0 + r) * NF_ + h * 64 + half * 32];
#pragma unroll
        for (int u = 0; u < 8; u++) {
            const int d = half * 32 + u * 4;
            float4 qv = *(const float4*)&qp[u * 4];
            qs[(d + 0) * 132 + r] = qv.x * 0.125f;
            qs[(d + 1) * 132 + r] = qv.y * 0.125f;
            qs[(d + 2) * 132 + r] = qv.z * 0.125f;
            qs[(d + 3) * 132 + r] = qv.w * 0.125f;
        }
    }

    float acc[8][4] = {};
    float mrun[8], lrun[8];
#pragma unroll
    for (int i = 0; i < 8; i++) { mrun[i] = -1e30f; lrun[i] = 0.0f; }

    const float4* qs4 = (const float4*)qs;
    const float4* ks4 = (const float4*)ks;
    const float4* ps4 = (const float4*)ps;
    const float4* vs4 = (const float4*)vs;

    const int ntiles = 2 * qt + 2;
    for (int kt = 0; kt < ntiles; kt++) {
        const int k0 = kt * 64;
        __syncthreads();
        {
            const int c = tid & 63, gq = tid >> 6;
            const float* kp = &g_qkv[(size_t)(b * S_ + k0 + c) * NF_ + D_ + h * 64 + gq * 16];
            const float* vp = &g_qkv[(size_t)(b * S_ + k0 + c) * NF_ + 2 * D_ + h * 64 + gq * 16];
#pragma unroll
            for (int u = 0; u < 4; u++) {
                const int d = gq * 16 + u * 4;
                float4 kv = *(const float4*)&kp[u * 4];
                ks[(d + 0) * 68 + c] = kv.x;
                ks[(d + 1) * 68 + c] = kv.y;
                ks[(d + 2) * 68 + c] = kv.z;
                ks[(d + 3) * 68 + c] = kv.w;
                *(float4*)&vs[c * 68 + d] = *(const float4*)&vp[u * 4];
            }
        }
        __syncthreads();

        float s[8][4] = {};
#pragma unroll
        for (int d = 0; d < 64; d++) {
            float4 q0v = qs4[d * 33 + ty * 2];
            float4 q1v = qs4[d * 33 + ty * 2 + 1];
            float4 kv  = ks4[d * 17 + tx];
            float qa[8] = {q0v.x, q0v.y, q0v.z, q0v.w, q1v.x, q1v.y, q1v.z, q1v.w};
            float kb[4] = {kv.x, kv.y, kv.z, kv.w};
#pragma unroll
            for (int i = 0; i < 8; i++)
#pragma unroll
                for (int j = 0; j < 4; j++)
                    s[i][j] += qa[i] * kb[j];
        }

        if (kt >= 2 * qt) {
#pragma unroll
            for (int i = 0; i < 8; i++)
#pragma unroll
                for (int j = 0; j < 4; j++)
                    if (k0 + tx * 4 + j > q0 + ty * 8 + i) s[i][j] = -1e30f;
        }

        float p[8][4];
#pragma unroll
        for (int i = 0; i < 8; i++) {
            float mloc = fmaxf(fmaxf(s[i][0], s[i][1]), fmaxf(s[i][2], s[i][3]));
#pragma unroll
            for (int w = 1; w < 16; w <<= 1)
                mloc = fmaxf(mloc, __shfl_xor_sync(0xffffffffu, mloc, w));
            const float mnew = fmaxf(mrun[i], mloc);
            const float alpha = __expf(mrun[i] - mnew);
            mrun[i] = mnew;
            float lloc = 0.0f;
#pragma unroll
            for (int j = 0; j < 4; j++) { p[i][j] = __expf(s[i][j] - mnew); lloc += p[i][j]; }
#pragma unroll
            for (int w = 1; w < 16; w <<= 1)
                lloc += __shfl_xor_sync(0xffffffffu, lloc, w);
            lrun[i] = lrun[i] * alpha + lloc;
#pragma unroll
            for (int j = 0; j < 4; j++) acc[i][j] *= alpha;
        }

#pragma unroll
        for (int j = 0; j < 4; j++) {
            const int c = tx * 4 + j;
            *(float4*)&ps[c * 132 + ty * 8]     = make_float4(p[0][j], p[1][j], p[2][j], p[3][j]);
            *(float4*)&ps[c * 132 + ty * 8 + 4] = make_float4(p[4][j], p[5][j], p[6][j], p[7][j]);
        }
        __syncthreads();

#pragma unroll
        for (int c = 0; c < 64; c++) {
            float4 p0v = ps4[c * 33 + ty * 2];
            float4 p1v = ps4[c * 33 + ty * 2 + 1];
            float4 vv  = vs4[c * 17 + tx];
            float pa[8] = {p0v.x, p0v.y, p0v.z, p0v.w, p1v.x, p1v.y, p1v.z, p1v.w};
#pragma unroll
            for (int i = 0; i < 8; i++) {
                acc[i][0] += pa[i] * vv.x;
                acc[i][1] += pa[i] * vv.y;
                acc[i][2] += pa[i] * vv.z;
                acc[i][3] += pa[i] * vv.w;
            }
        }
    }

    // epilogue: write z split into bf16 hi/lo directly
#pragma unroll
    for (int i = 0; i < 8; i++) {
        const float inv = 1.0f / lrun[i];
        float v[4] = {acc[i][0] * inv, acc[i][1] * inv, acc[i][2] * inv, acc[i][3] * inv};
        __nv_bfloat16 hh[4], ll[4];
#pragma unroll
        for (int j = 0; j < 4; j++) {
            hh[j] = __float2bfloat16(v[j]);
            ll[j] = __float2bfloat16(v[j] - __bfloat162float(hh[j]));
        }
        const size_t o = (size_t)(b * S_ + q0 + ty * 8 + i) * D_ + h * 64 + tx * 4;
        __nv_bfloat162 h0 = {hh[0], hh[1]}, h1 = {hh[2], hh[3]};
        __nv_bfloat162 l0 = {ll[0], ll[1]}, l1 = {ll[2], ll[3]};
        *(uint32_t*)&g_zh[o]     = *(uint32_t*)&h0;
        *(uint32_t*)&g_zh[o + 2] = *(uint32_t*)&h1;
        *(uint32_t*)&g_zl[o]     = *(uint32_t*)&l0;
        *(uint32_t*)&g_zl[o + 2] = *(uint32_t*)&l1;
    }
}

// --------------------------------- launch ----------------------------------
extern "C" void kernel_launch(void* const* d_in, const int* in_sizes, int n_in,
                              void* d_out, int out_size) {
    const float* X  = (const float*)d_in[0];
    const float* Wq = (const float*)d_in[1];
    const float* Wk = (const float*)d_in[2];
    const float* Wv = (const float*)d_in[3];
    const float* Wo = (const float*)d_in[4];
    const float* bq = (const float*)d_in[5];
    const float* bk = (const float*)d_in[6];
    const float* bv = (const float*)d_in[7];
    const float* bo = (const float*)d_in[8];
    float* out = (float*)d_out;

    const int attn_smem = (64 * 132 + 64 * 68 + 64 * 68 + 64 * 132) * 4;
    static bool attr_set = false;
    if (!attr_set) {
        cudaFuncSetAttribute(attn_kernel,
                             cudaFuncAttributeMaxDynamicSharedMemorySize, attn_smem);
        attr_set = true;
    }

    static __nv_bfloat16 *xh = nullptr, *xl, *zh, *zl, *wth, *wtl, *woh, *wol;
    static float *qkv, *fb;
    if (!xh) {
        cudaGetSymbolAddress((void**)&xh,  g_xh);
        cudaGetSymbolAddress((void**)&xl,  g_xl);
        cudaGetSymbolAddress((void**)&zh,  g_zh);
        cudaGetSymbolAddress((void**)&zl,  g_zl);
        cudaGetSymbolAddress((void**)&wth, g_wth);
        cudaGetSymbolAddress((void**)&wtl, g_wtl);
        cudaGetSymbolAddress((void**)&woh, g_woh);
        cudaGetSymbolAddress((void**)&wol, g_wol);
        cudaGetSymbolAddress((void**)&qkv, g_qkv);
        cudaGetSymbolAddress((void**)&fb,  g_fb);
    }

    // 1) conversions
    split_kernel<<<(M_ * D_) / (256 * 8), 256>>>(X, xh, xl, M_ * D_);
    trans_qkv_kernel<<<dim3(D_ / 64, 3 * H_), 256>>>(Wq, Wk, Wv);
    trans_wo_kernel<<<dim3(D_ / 64, D_ / 64), 256>>>(Wo);
    fuse_bias_kernel<<<(NF_ + 255) / 256, 256>>>(bq, bk, bv);

    // 2) fused QKV projection (HMMA tensor cores)
    gemm_mma_kernel<<<dim3(NF_ / 128, M_ / 128), 256>>>(
        xh, xl, wth, wtl, qkv, NF_, fb);

    // 3) causal attention (fp32), writes zh/zl bf16 split
    attn_kernel<<<dim3(S_ / 128, B_ * H_), 256, attn_smem>>>();

    // 4) output projection (HMMA tensor cores)
    gemm_mma_kernel<<<dim3(D_ / 128, M_ / 128), 256>>>(
        zh, zl, woh, wol, out, D_, bo);
}

// round 5
// speedup vs baseline: 2.4466x; 1.5783x over previous
#include <cuda_runtime.h>
#include <cuda_bf16.h>
#include <cstdint>

#define B_  4
#define S_  2048
#define D_  768
#define H_  12
#define M_  (B_ * S_)     // 8192
#define NF_ (3 * D_)      // 2304 fused qkv cols

// ------------------------- device scratch (no allocs) -----------------------
__device__ float          g_qkv[(size_t)M_ * NF_];   // fused q|k|v fp32
__device__ __nv_bfloat16  g_xh [(size_t)M_ * D_];    // residual hi/lo
__device__ __nv_bfloat16  g_xl [(size_t)M_ * D_];
__device__ __nv_bfloat16  g_zh [(size_t)M_ * D_];    // attention out hi/lo
__device__ __nv_bfloat16  g_zl [(size_t)M_ * D_];
__device__ __nv_bfloat16  g_wth[(size_t)NF_ * D_];   // W_{q,k,v}^T  [n][d]
__device__ __nv_bfloat16  g_wtl[(size_t)NF_ * D_];
__device__ __nv_bfloat16  g_woh[(size_t)D_ * D_];    // W_O^T [d_out][he]
__device__ __nv_bfloat16  g_wol[(size_t)D_ * D_];
__device__ float          g_fb [NF_];                // fused qkv bias

// ------------------------------ PTX helpers --------------------------------
__device__ __forceinline__ uint32_t smem_u32(const void* p) {
    uint32_t a;
    asm("{ .reg .u64 t; cvta.to.shared.u64 t, %1; cvt.u32.u64 %0, t; }"
        : "=r"(a) : "l"(p));
    return a;
}
__device__ __forceinline__ void ldsm_x4(uint32_t* r, uint32_t addr) {
    asm volatile("ldmatrix.sync.aligned.m8n8.x4.shared.b16 {%0,%1,%2,%3}, [%4];"
                 : "=r"(r[0]), "=r"(r[1]), "=r"(r[2]), "=r"(r[3]) : "r"(addr));
}
__device__ __forceinline__ void mma16816(float* c, const uint32_t* a,
                                         uint32_t b0, uint32_t b1) {
    asm volatile(
        "mma.sync.aligned.m16n8k16.row.col.f32.bf16.bf16.f32 "
        "{%0,%1,%2,%3}, {%4,%5,%6,%7}, {%8,%9}, {%0,%1,%2,%3};"
        : "+f"(c[0]), "+f"(c[1]), "+f"(c[2]), "+f"(c[3])
        : "r"(a[0]), "r"(a[1]), "r"(a[2]), "r"(a[3]), "r"(b0), "r"(b1));
}
// split two floats into packed bf16 hi pair + residual lo pair
__device__ __forceinline__ void split2(float a, float b, uint32_t& hi, uint32_t& lo) {
    __nv_bfloat16 ha = __float2bfloat16(a), hb = __float2bfloat16(b);
    __nv_bfloat16 la = __float2bfloat16(a - __bfloat162float(ha));
    __nv_bfloat16 lb = __float2bfloat16(b - __bfloat162float(hb));
    __nv_bfloat162 hp = {ha, hb}, lp = {la, lb};
    hi = *(uint32_t*)&hp; lo = *(uint32_t*)&lp;
}

// --------------------------- conversion kernels ----------------------------
__global__ void split_kernel(const float* __restrict__ src,
                             __nv_bfloat16* __restrict__ dh,
                             __nv_bfloat16* __restrict__ dl, int n) {
    int i8 = (blockIdx.x * 256 + threadIdx.x) * 8;
    if (i8 >= n) return;
    float4 v0 = *(const float4*)&src[i8];
    float4 v1 = *(const float4*)&src[i8 + 4];
    float v[8] = {v0.x, v0.y, v0.z, v0.w, v1.x, v1.y, v1.z, v1.w};
    __align__(16) __nv_bfloat16 h[8], l[8];
#pragma unroll
    for (int j = 0; j < 8; j++) {
        h[j] = __float2bfloat16(v[j]);
        l[j] = __float2bfloat16(v[j] - __bfloat162float(h[j]));
    }
    *(uint4*)&dh[i8] = *(uint4*)h;
    *(uint4*)&dl[i8] = *(uint4*)l;
}

__device__ __forceinline__ void trans_tile(const float* src, int src_ld,
                                           __nv_bfloat16* dh, __nv_bfloat16* dl,
                                           int dst_ld, int r0, int c0, int base) {
    __shared__ float ts[64 * 65];
    const int tid = threadIdx.x;
#pragma unroll
    for (int it = 0; it < 16; it++) {
        int flat = tid + it * 256;
        int i = flat >> 6, c = flat & 63;
        ts[c * 65 + i] = src[(size_t)(r0 + i) * src_ld + c0 + c];
    }
    __syncthreads();
#pragma unroll
    for (int it = 0; it < 8; it++) {
        int flat = tid + it * 256;
        int c = flat >> 5, rj = flat & 31;
        uint32_t hp, lp;
        split2(ts[c * 65 + rj * 2], ts[c * 65 + rj * 2 + 1], hp, lp);
        size_t o = (size_t)(base + c0 + c) * dst_ld + r0 + rj * 2;
        *(uint32_t*)&dh[o] = hp;
        *(uint32_t*)&dl[o] = lp;
    }
}

__global__ void trans_qkv_kernel(const float* __restrict__ Wq,
                                 const float* __restrict__ Wk,
                                 const float* __restrict__ Wv) {
    const int by = blockIdx.y;
    const int t = by / H_, h = by % H_;
    const float* src = ((t == 0) ? Wq : (t == 1) ? Wk : Wv) + (size_t)h * D_ * 64;
    trans_tile(src, 64, g_wth, g_wtl, D_, blockIdx.x * 64, 0, t * D_ + h * 64);
}
__global__ void trans_wo_kernel(const float* __restrict__ Wo) {
    trans_tile(Wo, D_, g_woh, g_wol, D_, blockIdx.x * 64, blockIdx.y * 64, 0);
}
__global__ void fuse_bias_kernel(const float* __restrict__ bq,
                                 const float* __restrict__ bk,
                                 const float* __restrict__ bv) {
    int n = blockIdx.x * 256 + threadIdx.x;
    if (n < NF_) g_fb[n] = (n < D_) ? bq[n] : (n < 2 * D_) ? bk[n - D_] : bv[n - 2 * D_];
}

// ------------------------ mma.sync bf16x3 GEMM (verified R4) ----------------
__global__ __launch_bounds__(256, 1)
void gemm_mma_kernel(const __nv_bfloat16* __restrict__ Ah,
                     const __nv_bfloat16* __restrict__ Al,
                     const __nv_bfloat16* __restrict__ Bh,
                     const __nv_bfloat16* __restrict__ Bl,
                     float* __restrict__ out, int ld_out,
                     const float* __restrict__ bias) {
    __shared__ __align__(16) __nv_bfloat16 smt[4 * 128 * 40];
    const uint32_t sb = smem_u32(smt);

    const int tid  = threadIdx.x;
    const int wid  = tid >> 5;
    const int lane = tid & 31;
    const int wr   = wid >> 2;
    const int wc   = wid & 3;
    const size_t m0 = blockIdx.y * 128;
    const size_t n0 = blockIdx.x * 128;

    const int lr  = tid >> 2;
    const int lc8 = tid & 3;

    const __nv_bfloat16* srcs[4] = {Ah, Al, Bh, Bl};
    const size_t rbase[4] = {m0, m0, n0, n0};

    float acc[4][4][4] = {};

#pragma unroll
    for (int p = 0; p < 4; p++)
#pragma unroll
        for (int it = 0; it < 2; it++) {
            int r = lr + it * 64;
            uint4 v = *(const uint4*)&srcs[p][(rbase[p] + r) * D_ + lc8 * 8];
            *(uint4*)&smt[p * 5120 + r * 40 + lc8 * 8] = v;
        }
    __syncthreads();

    const int lrow = lane & 15;
    const int lcol = (lane >> 4) * 8;

    for (int kt = 0; kt < 24; kt++) {
        uint4 pref[8];
        if (kt < 23) {
            const int k0n = (kt + 1) * 32;
#pragma unroll
            for (int p = 0; p < 4; p++)
#pragma unroll
                for (int it = 0; it < 2; it++) {
                    int r = lr + it * 64;
                    pref[p * 2 + it] =
                        *(const uint4*)&srcs[p][(rbase[p] + r) * D_ + k0n + lc8 * 8];
                }
        }

#pragma unroll
        for (int ks = 0; ks < 2; ks++) {
            const int kb = ks * 16;
            uint32_t aFh[4][4], aFl[4][4], bFh[2][4], bFl[2][4];
#pragma unroll
            for (int mt = 0; mt < 4; mt++) {
                int row = wr * 64 + mt * 16 + lrow;
                ldsm_x4(aFh[mt], sb + (0 * 5120 + row * 40 + kb + lcol) * 2);
                ldsm_x4(aFl[mt], sb + (1 * 5120 + row * 40 + kb + lcol) * 2);
            }
#pragma unroll
            for (int np = 0; np < 2; np++) {
                int row = wc * 32 + np * 16 + lrow;
                ldsm_x4(bFh[np], sb + (2 * 5120 + row * 40 + kb + lcol) * 2);
                ldsm_x4(bFl[np], sb + (3 * 5120 + row * 40 + kb + lcol) * 2);
            }
#pragma unroll
            for (int mt = 0; mt < 4; mt++)
#pragma unroll
                for (int nt = 0; nt < 4; nt++) {
                    const int np = nt >> 1, ni = nt & 1;
                    mma16816(acc[mt][nt], aFh[mt], bFh[np][ni], bFh[np][ni + 2]);
                    mma16816(acc[mt][nt], aFh[mt], bFl[np][ni], bFl[np][ni + 2]);
                    mma16816(acc[mt][nt], aFl[mt], bFh[np][ni], bFh[np][ni + 2]);
                }
        }
        __syncthreads();
        if (kt < 23) {
#pragma unroll
            for (int p = 0; p < 4; p++)
#pragma unroll
                for (int it = 0; it < 2; it++) {
                    int r = lr + it * 64;
                    *(uint4*)&smt[p * 5120 + r * 40 + lc8 * 8] = pref[p * 2 + it];
                }
            __syncthreads();
        }
    }

    const int g = lane >> 2;
    const int cb = (lane & 3) * 2;
#pragma unroll
    for (int mt = 0; mt < 4; mt++)
#pragma unroll
        for (int nt = 0; nt < 4; nt++) {
            const size_t col = n0 + wc * 32 + nt * 8 + cb;
            float2 bv = *(const float2*)&bias[col];
            const size_t r0 = m0 + wr * 64 + mt * 16 + g;
            float2 v0 = {acc[mt][nt][0] + bv.x, acc[mt][nt][1] + bv.y};
            float2 v1 = {acc[mt][nt][2] + bv.x, acc[mt][nt][3] + bv.y};
            *(float2*)&out[r0 * ld_out + col]       = v0;
            *(float2*)&out[(r0 + 8) * ld_out + col] = v1;
        }
}

// ------------------- mma.sync bf16x3 causal flash attention -----------------
// CTA: (b, h, 128 q-rows). 8 warps, warp owns 16 rows. kv tiles of 64.
// smem aliased: Q phase = Qh[128][72] | Ql[128][72];
//               KV phase = Kh[64][72] | Kl | VTh[64][72] (V transposed) | VTl.
#define KH_  0
#define KL_  (64 * 72)
#define VTH_ (2 * 64 * 72)
#define VTL_ (3 * 64 * 72)
__global__ __launch_bounds__(256, 1) void attn_mma_kernel() {
    __shared__ __align__(16) __nv_bfloat16 sm[4 * 64 * 72];
    const uint32_t sb = smem_u32(sm);

    const int tid = threadIdx.x, wid = tid >> 5, lane = tid & 31;
    const int qt = gridDim.x - 1 - blockIdx.x;   // heavy tiles first
    const int bh = blockIdx.y;
    const int b = bh / H_, h = bh % H_;
    const int q0 = qt * 128;

    // ---- phase 1: Q (scaled 0.125) split hi/lo into smem ----
    {
        const int r = tid & 127, gq = tid >> 7;   // gq: dh half
        const float* qp = &g_qkv[(size_t)(b * S_ + q0 + r) * NF_ + h * 64 + gq * 32];
#pragma unroll
        for (int u = 0; u < 8; u++) {
            float4 v = *(const float4*)&qp[u * 4];
            uint32_t h01, l01, h23, l23;
            split2(v.x * 0.125f, v.y * 0.125f, h01, l01);
            split2(v.z * 0.125f, v.w * 0.125f, h23, l23);
            const int base = r * 72 + gq * 32 + u * 4;
            *(uint32_t*)&sm[base]            = h01;
            *(uint32_t*)&sm[base + 2]        = h23;
            *(uint32_t*)&sm[9216 + base]     = l01;
            *(uint32_t*)&sm[9216 + base + 2] = l23;
        }
    }
    __syncthreads();

    // ---- Q fragments to registers (A side), once ----
    uint32_t aQh[4][4], aQl[4][4];
    {
        const int row = wid * 16 + (lane & 15);
        const int cb8 = (lane >> 4) * 8;
#pragma unroll
        for (int kk = 0; kk < 4; kk++) {
            ldsm_x4(aQh[kk], sb + (row * 72 + kk * 16 + cb8) * 2);
            ldsm_x4(aQl[kk], sb + (9216 + row * 72 + kk * 16 + cb8) * 2);
        }
    }
    __syncthreads();   // smem now reusable for K/V

    float oacc[8][4] = {};
    float mrun[2] = {-1e30f, -1e30f}, lrun[2] = {0.0f, 0.0f};

    const int lrw = lane & 15;
    const int cb8 = (lane >> 4) * 8;
    const int ntiles = 2 * qt + 2;

    for (int kt = 0; kt < ntiles; kt++) {
        const int k0 = kt * 64;

        // ---- load K (split, [kv][dh]) and V (split, transposed [dh][kv]) ----
        {
            const int c = tid & 63, grp = tid >> 6;   // grp: 16-dh slice
            const float* kp = &g_qkv[(size_t)(b * S_ + k0 + c) * NF_ + D_ + h * 64 + grp * 16];
            const float* vp = &g_qkv[(size_t)(b * S_ + k0 + c) * NF_ + 2 * D_ + h * 64 + grp * 16];
#pragma unroll
            for (int u = 0; u < 4; u++) {
                const int d = grp * 16 + u * 4;
                float4 kv = *(const float4*)&kp[u * 4];
                uint32_t h01, l01, h23, l23;
                split2(kv.x, kv.y, h01, l01);
                split2(kv.z, kv.w, h23, l23);
                *(uint32_t*)&sm[KH_ + c * 72 + d]     = h01;
                *(uint32_t*)&sm[KH_ + c * 72 + d + 2] = h23;
                *(uint32_t*)&sm[KL_ + c * 72 + d]     = l01;
                *(uint32_t*)&sm[KL_ + c * 72 + d + 2] = l23;
                float4 vv = *(const float4*)&vp[u * 4];
                float vf[4] = {vv.x, vv.y, vv.z, vv.w};
#pragma unroll
                for (int i = 0; i < 4; i++) {
                    __nv_bfloat16 vh = __float2bfloat16(vf[i]);
                    __nv_bfloat16 vl = __float2bfloat16(vf[i] - __bfloat162float(vh));
                    sm[VTH_ + (d + i) * 72 + c] = vh;
                    sm[VTL_ + (d + i) * 72 + c] = vl;
                }
            }
        }
        __syncthreads();

        // ---- S = Q K^T (bf16x3) ----
        float sacc[8][4] = {};
#pragma unroll
        for (int kk = 0; kk < 4; kk++) {
#pragma unroll
            for (int np = 0; np < 4; np++) {
                uint32_t kbh[4], kbl[4];
                ldsm_x4(kbh, sb + (KH_ + (np * 16 + lrw) * 72 + kk * 16 + cb8) * 2);
                ldsm_x4(kbl, sb + (KL_ + (np * 16 + lrw) * 72 + kk * 16 + cb8) * 2);
#pragma unroll
                for (int ni = 0; ni < 2; ni++) {
                    const int nt = np * 2 + ni;
                    mma16816(sacc[nt], aQh[kk], kbh[ni], kbh[ni + 2]);
                    mma16816(sacc[nt], aQh[kk], kbl[ni], kbl[ni + 2]);
                    mma16816(sacc[nt], aQl[kk], kbh[ni], kbh[ni + 2]);
                }
            }
        }

        // ---- causal mask (only last two tiles) ----
        if (kt >= 2 * qt) {
#pragma unroll
            for (int nt = 0; nt < 8; nt++)
#pragma unroll
                for (int e = 0; e < 4; e++) {
                    const int row = q0 + wid * 16 + (lane >> 2) + (e >> 1) * 8;
                    const int col = k0 + nt * 8 + (lane & 3) * 2 + (e & 1);
                    if (col > row) sacc[nt][e] = -1e30f;
                }
        }

        // ---- streaming softmax (rows owned by lane quads) ----
#pragma unroll
        for (int rg = 0; rg < 2; rg++) {
            float mloc = -1e30f;
#pragma unroll
            for (int nt = 0; nt < 8; nt++)
                mloc = fmaxf(mloc, fmaxf(sacc[nt][rg * 2], sacc[nt][rg * 2 + 1]));
            mloc = fmaxf(mloc, __shfl_xor_sync(0xffffffffu, mloc, 1));
            mloc = fmaxf(mloc, __shfl_xor_sync(0xffffffffu, mloc, 2));
            const float mnew = fmaxf(mrun[rg], mloc);
            const float alpha = __expf(mrun[rg] - mnew);
            float lloc = 0.0f;
#pragma unroll
            for (int nt = 0; nt < 8; nt++) {
                sacc[nt][rg * 2]     = __expf(sacc[nt][rg * 2] - mnew);
                sacc[nt][rg * 2 + 1] = __expf(sacc[nt][rg * 2 + 1] - mnew);
                lloc += sacc[nt][rg * 2] + sacc[nt][rg * 2 + 1];
            }
            lloc += __shfl_xor_sync(0xffffffffu, lloc, 1);
            lloc += __shfl_xor_sync(0xffffffffu, lloc, 2);
            lrun[rg] = lrun[rg] * alpha + lloc;
            mrun[rg] = mnew;
#pragma unroll
            for (int dt = 0; dt < 8; dt++) {
                oacc[dt][rg * 2]     *= alpha;
                oacc[dt][rg * 2 + 1] *= alpha;
            }
        }

        // ---- repack P (C-frag) -> A-frags, split hi/lo ----
        uint32_t aPh[4][4], aPl[4][4];
#pragma unroll
        for (int kk2 = 0; kk2 < 4; kk2++) {
            split2(sacc[kk2 * 2][0],     sacc[kk2 * 2][1],     aPh[kk2][0], aPl[kk2][0]);
            split2(sacc[kk2 * 2][2],     sacc[kk2 * 2][3],     aPh[kk2][1], aPl[kk2][1]);
            split2(sacc[kk2 * 2 + 1][0], sacc[kk2 * 2 + 1][1], aPh[kk2][2], aPl[kk2][2]);
            split2(sacc[kk2 * 2 + 1][2], sacc[kk2 * 2 + 1][3], aPh[kk2][3], aPl[kk2][3]);
        }

        // ---- O += P V (bf16x3) ----
#pragma unroll
        for (int kk2 = 0; kk2 < 4; kk2++) {
#pragma unroll
            for (int dp = 0; dp < 4; dp++) {
                uint32_t vbh[4], vbl[4];
                ldsm_x4(vbh, sb + (VTH_ + (dp * 16 + lrw) * 72 + kk2 * 16 + cb8) * 2);
                ldsm_x4(vbl, sb + (VTL_ + (dp * 16 + lrw) * 72 + kk2 * 16 + cb8) * 2);
#pragma unroll
                for (int ni = 0; ni < 2; ni++) {
                    const int dt = dp * 2 + ni;
                    mma16816(oacc[dt], aPh[kk2], vbh[ni], vbh[ni + 2]);
                    mma16816(oacc[dt], aPh[kk2], vbl[ni], vbl[ni + 2]);
                    mma16816(oacc[dt], aPl[kk2], vbh[ni], vbh[ni + 2]);
                }
            }
        }
        __syncthreads();   // before next tile overwrites smem
    }

    // ---- epilogue: z = O / l, split bf16 hi/lo ----
#pragma unroll
    for (int rg = 0; rg < 2; rg++) {
        const float inv = 1.0f / lrun[rg];
        const int row = q0 + wid * 16 + (lane >> 2) + rg * 8;
#pragma unroll
        for (int dt = 0; dt < 8; dt++) {
            const size_t o = (size_t)(b * S_ + row) * D_ + h * 64 + dt * 8 + (lane & 3) * 2;
            uint32_t hp, lp;
            split2(oacc[dt][rg * 2] * inv, oacc[dt][rg * 2 + 1] * inv, hp, lp);
            *(uint32_t*)&g_zh[o] = hp;
            *(uint32_t*)&g_zl[o] = lp;
        }
    }
}

// --------------------------------- launch ----------------------------------
extern "C" void kernel_launch(void* const* d_in, const int* in_sizes, int n_in,
                              void* d_out, int out_size) {
    const float* X  = (const float*)d_in[0];
    const float* Wq = (const float*)d_in[1];
    const float* Wk = (const float*)d_in[2];
    const float* Wv = (const float*)d_in[3];
    const float* Wo = (const float*)d_in[4];
    const float* bq = (const float*)d_in[5];
    const float* bk = (const float*)d_in[6];
    const float* bv = (const float*)d_in[7];
    const float* bo = (const float*)d_in[8];
    float* out = (float*)d_out;

    static __nv_bfloat16 *xh = nullptr, *xl, *zh, *zl, *wth, *wtl, *woh, *wol;
    static float *qkv, *fb;
    if (!xh) {
        cudaGetSymbolAddress((void**)&xh,  g_xh);
        cudaGetSymbolAddress((void**)&xl,  g_xl);
        cudaGetSymbolAddress((void**)&zh,  g_zh);
        cudaGetSymbolAddress((void**)&zl,  g_zl);
        cudaGetSymbolAddress((void**)&wth, g_wth);
        cudaGetSymbolAddress((void**)&wtl, g_wtl);
        cudaGetSymbolAddress((void**)&woh, g_woh);
        cudaGetSymbolAddress((void**)&wol, g_wol);
        cudaGetSymbolAddress((void**)&qkv, g_qkv);
        cudaGetSymbolAddress((void**)&fb,  g_fb);
    }

    // 1) conversions
    split_kernel<<<(M_ * D_) / (256 * 8), 256>>>(X, xh, xl, M_ * D_);
    trans_qkv_kernel<<<dim3(D_ / 64, 3 * H_), 256>>>(Wq, Wk, Wv);
    trans_wo_kernel<<<dim3(D_ / 64, D_ / 64), 256>>>(Wo);
    fuse_bias_kernel<<<(NF_ + 255) / 256, 256>>>(bq, bk, bv);

    // 2) fused QKV projection (tensor cores)
    gemm_mma_kernel<<<dim3(NF_ / 128, M_ / 128), 256>>>(
        xh, xl, wth, wtl, qkv, NF_, fb);

    // 3) causal attention (tensor cores)
    attn_mma_kernel<<<dim3(S_ / 128, B_ * H_), 256>>>();

    // 4) output projection (tensor cores)
    gemm_mma_kernel<<<dim3(D_ / 128, M_ / 128), 256>>>(
        zh, zl, woh, wol, out, D_, bo);
}

// round 6
// speedup vs baseline: 2.7739x; 1.1338x over previous
#include <cuda_runtime.h>
#include <cuda_bf16.h>
#include <cstdint>

#define B_  4
#define S_  2048
#define D_  768
#define H_  12
#define M_  (B_ * S_)     // 8192
#define NF_ (3 * D_)      // 2304 fused qkv cols

// ------------------------- device scratch (no allocs) -----------------------
__device__ __nv_bfloat16  g_xh [(size_t)M_ * D_];    // residual hi/lo
__device__ __nv_bfloat16  g_xl [(size_t)M_ * D_];
__device__ __nv_bfloat16  g_qh [(size_t)M_ * D_];    // q (pre-scaled) hi/lo
__device__ __nv_bfloat16  g_ql [(size_t)M_ * D_];
__device__ __nv_bfloat16  g_kh [(size_t)M_ * D_];    // k hi/lo
__device__ __nv_bfloat16  g_kl [(size_t)M_ * D_];
__device__ __nv_bfloat16  g_vh [(size_t)M_ * D_];    // v hi/lo (natural)
__device__ __nv_bfloat16  g_vl [(size_t)M_ * D_];
__device__ __nv_bfloat16  g_vth[(size_t)B_ * H_ * 64 * S_];  // v^T [bh][dh][s]
__device__ __nv_bfloat16  g_vtl[(size_t)B_ * H_ * 64 * S_];
__device__ __nv_bfloat16  g_zh [(size_t)M_ * D_];    // attention out hi/lo
__device__ __nv_bfloat16  g_zl [(size_t)M_ * D_];
__device__ __nv_bfloat16  g_wth[(size_t)NF_ * D_];   // W_{q,k,v}^T  [n][d]
__device__ __nv_bfloat16  g_wtl[(size_t)NF_ * D_];
__device__ __nv_bfloat16  g_woh[(size_t)D_ * D_];    // W_O^T [d_out][he]
__device__ __nv_bfloat16  g_wol[(size_t)D_ * D_];
__device__ float          g_fb [NF_];                // fused qkv bias

// ------------------------------ PTX helpers --------------------------------
__device__ __forceinline__ uint32_t smem_u32(const void* p) {
    uint32_t a;
    asm("{ .reg .u64 t; cvta.to.shared.u64 t, %1; cvt.u32.u64 %0, t; }"
        : "=r"(a) : "l"(p));
    return a;
}
__device__ __forceinline__ void ldsm_x4(uint32_t* r, uint32_t addr) {
    asm volatile("ldmatrix.sync.aligned.m8n8.x4.shared.b16 {%0,%1,%2,%3}, [%4];"
                 : "=r"(r[0]), "=r"(r[1]), "=r"(r[2]), "=r"(r[3]) : "r"(addr));
}
__device__ __forceinline__ void mma16816(float* c, const uint32_t* a,
                                         uint32_t b0, uint32_t b1) {
    asm volatile(
        "mma.sync.aligned.m16n8k16.row.col.f32.bf16.bf16.f32 "
        "{%0,%1,%2,%3}, {%4,%5,%6,%7}, {%8,%9}, {%0,%1,%2,%3};"
        : "+f"(c[0]), "+f"(c[1]), "+f"(c[2]), "+f"(c[3])
        : "r"(a[0]), "r"(a[1]), "r"(a[2]), "r"(a[3]), "r"(b0), "r"(b1));
}
__device__ __forceinline__ void split2(float a, float b, uint32_t& hi, uint32_t& lo) {
    __nv_bfloat16 ha = __float2bfloat16(a), hb = __float2bfloat16(b);
    __nv_bfloat16 la = __float2bfloat16(a - __bfloat162float(ha));
    __nv_bfloat16 lb = __float2bfloat16(b - __bfloat162float(hb));
    __nv_bfloat162 hp = {ha, hb}, lp = {la, lb};
    hi = *(uint32_t*)&hp; lo = *(uint32_t*)&lp;
}
#define CP_ASYNC16(dst, src) \
    asm volatile("cp.async.cg.shared.global [%0], [%1], 16;" :: "r"(dst), "l"(src))
#define CP_COMMIT() asm volatile("cp.async.commit_group;" ::: "memory")
#define CP_WAIT(n)  asm volatile("cp.async.wait_group %0;" :: "n"(n) : "memory")

// --------------------------- conversion kernels ----------------------------
__global__ void split_kernel(const float* __restrict__ src,
                             __nv_bfloat16* __restrict__ dh,
                             __nv_bfloat16* __restrict__ dl, int n) {
    int i8 = (blockIdx.x * 256 + threadIdx.x) * 8;
    if (i8 >= n) return;
    float4 v0 = *(const float4*)&src[i8];
    float4 v1 = *(const float4*)&src[i8 + 4];
    float v[8] = {v0.x, v0.y, v0.z, v0.w, v1.x, v1.y, v1.z, v1.w};
    __align__(16) __nv_bfloat16 h[8], l[8];
#pragma unroll
    for (int j = 0; j < 8; j++) {
        h[j] = __float2bfloat16(v[j]);
        l[j] = __float2bfloat16(v[j] - __bfloat162float(h[j]));
    }
    *(uint4*)&dh[i8] = *(uint4*)h;
    *(uint4*)&dl[i8] = *(uint4*)l;
}

__device__ __forceinline__ void trans_tile(const float* src, int src_ld,
                                           __nv_bfloat16* dh, __nv_bfloat16* dl,
                                           int dst_ld, int r0, int c0, int base) {
    __shared__ float ts[64 * 65];
    const int tid = threadIdx.x;
#pragma unroll
    for (int it = 0; it < 16; it++) {
        int flat = tid + it * 256;
        int i = flat >> 6, c = flat & 63;
        ts[c * 65 + i] = src[(size_t)(r0 + i) * src_ld + c0 + c];
    }
    __syncthreads();
#pragma unroll
    for (int it = 0; it < 8; it++) {
        int flat = tid + it * 256;
        int c = flat >> 5, rj = flat & 31;
        uint32_t hp, lp;
        split2(ts[c * 65 + rj * 2], ts[c * 65 + rj * 2 + 1], hp, lp);
        size_t o = (size_t)(base + c0 + c) * dst_ld + r0 + rj * 2;
        *(uint32_t*)&dh[o] = hp;
        *(uint32_t*)&dl[o] = lp;
    }
}

__global__ void trans_qkv_kernel(const float* __restrict__ Wq,
                                 const float* __restrict__ Wk,
                                 const float* __restrict__ Wv) {
    const int by = blockIdx.y;
    const int t = by / H_, h = by % H_;
    const float* src = ((t == 0) ? Wq : (t == 1) ? Wk : Wv) + (size_t)h * D_ * 64;
    trans_tile(src, 64, g_wth, g_wtl, D_, blockIdx.x * 64, 0, t * D_ + h * 64);
}
__global__ void trans_wo_kernel(const float* __restrict__ Wo) {
    trans_tile(Wo, D_, g_woh, g_wol, D_, blockIdx.x * 64, blockIdx.y * 64, 0);
}
__global__ void fuse_bias_kernel(const float* __restrict__ bq,
                                 const float* __restrict__ bk,
                                 const float* __restrict__ bv) {
    int n = blockIdx.x * 256 + threadIdx.x;
    if (n < NF_) g_fb[n] = (n < D_) ? bq[n] : (n < 2 * D_) ? bk[n - D_] : bv[n - 2 * D_];
}

// V transpose: g_vh/g_vl [b][s][h*64+e] -> g_vth/g_vtl [(b*H+h)*64+e][s]
__global__ void trans_v_kernel() {
    __shared__ __nv_bfloat16 th[64 * 72], tl[64 * 72];
    const int s0 = blockIdx.x * 64;
    const int bh = blockIdx.y;
    const int b = bh / H_, h = bh % H_;
    const int tid = threadIdx.x;
#pragma unroll
    for (int it = 0; it < 8; it++) {          // load: uint32 over e-pairs
        int idx = tid + it * 256;             // < 2048
        int s = idx >> 5, e2 = idx & 31;
        uint32_t vh2 = *(const uint32_t*)&g_vh[(size_t)(b * S_ + s0 + s) * D_ + h * 64 + e2 * 2];
        uint32_t vl2 = *(const uint32_t*)&g_vl[(size_t)(b * S_ + s0 + s) * D_ + h * 64 + e2 * 2];
        __nv_bfloat162 hb = *(__nv_bfloat162*)&vh2;
        __nv_bfloat162 lb = *(__nv_bfloat162*)&vl2;
        th[(e2 * 2 + 0) * 72 + s] = hb.x;
        th[(e2 * 2 + 1) * 72 + s] = hb.y;
        tl[(e2 * 2 + 0) * 72 + s] = lb.x;
        tl[(e2 * 2 + 1) * 72 + s] = lb.y;
    }
    __syncthreads();
#pragma unroll
    for (int it = 0; it < 8; it++) {          // store: uint32 over s-pairs
        int idx = tid + it * 256;
        int e = idx >> 5, s2 = idx & 31;
        size_t o = ((size_t)bh * 64 + e) * S_ + s0 + s2 * 2;
        *(uint32_t*)&g_vth[o] = *(uint32_t*)&th[e * 72 + s2 * 2];
        *(uint32_t*)&g_vtl[o] = *(uint32_t*)&tl[e * 72 + s2 * 2];
    }
}

// ------------------------ mma.sync bf16x3 GEMM ------------------------------
// MODE 0: fp32 out + bias (output projection).
// MODE 1: split bf16 epilogue into g_qh/ql, g_kh/kl, g_vh/vl (q scaled 0.125).
template <int MODE>
__global__ __launch_bounds__(256, 1)
void gemm_mma_kernel(const __nv_bfloat16* __restrict__ Ah,
                     const __nv_bfloat16* __restrict__ Al,
                     const __nv_bfloat16* __restrict__ Bh,
                     const __nv_bfloat16* __restrict__ Bl,
                     float* __restrict__ out, int ld_out,
                     const float* __restrict__ bias) {
    __shared__ __align__(16) __nv_bfloat16 smt[4 * 128 * 40];
    const uint32_t sb = smem_u32(smt);

    const int tid  = threadIdx.x;
    const int wid  = tid >> 5;
    const int lane = tid & 31;
    const int wr   = wid >> 2;
    const int wc   = wid & 3;
    const size_t m0 = blockIdx.y * 128;
    const size_t n0 = blockIdx.x * 128;

    const int lr  = tid >> 2;
    const int lc8 = tid & 3;

    const __nv_bfloat16* srcs[4] = {Ah, Al, Bh, Bl};
    const size_t rbase[4] = {m0, m0, n0, n0};

    float acc[4][4][4] = {};

#pragma unroll
    for (int p = 0; p < 4; p++)
#pragma unroll
        for (int it = 0; it < 2; it++) {
            int r = lr + it * 64;
            uint4 v = *(const uint4*)&srcs[p][(rbase[p] + r) * D_ + lc8 * 8];
            *(uint4*)&smt[p * 5120 + r * 40 + lc8 * 8] = v;
        }
    __syncthreads();

    const int lrow = lane & 15;
    const int lcol = (lane >> 4) * 8;

    for (int kt = 0; kt < 24; kt++) {
        uint4 pref[8];
        if (kt < 23) {
            const int k0n = (kt + 1) * 32;
#pragma unroll
            for (int p = 0; p < 4; p++)
#pragma unroll
                for (int it = 0; it < 2; it++) {
                    int r = lr + it * 64;
                    pref[p * 2 + it] =
                        *(const uint4*)&srcs[p][(rbase[p] + r) * D_ + k0n + lc8 * 8];
                }
        }

#pragma unroll
        for (int ks = 0; ks < 2; ks++) {
            const int kb = ks * 16;
            uint32_t aFh[4][4], aFl[4][4], bFh[2][4], bFl[2][4];
#pragma unroll
            for (int mt = 0; mt < 4; mt++) {
                int row = wr * 64 + mt * 16 + lrow;
                ldsm_x4(aFh[mt], sb + (0 * 5120 + row * 40 + kb + lcol) * 2);
                ldsm_x4(aFl[mt], sb + (1 * 5120 + row * 40 + kb + lcol) * 2);
            }
#pragma unroll
            for (int np = 0; np < 2; np++) {
                int row = wc * 32 + np * 16 + lrow;
                ldsm_x4(bFh[np], sb + (2 * 5120 + row * 40 + kb + lcol) * 2);
                ldsm_x4(bFl[np], sb + (3 * 5120 + row * 40 + kb + lcol) * 2);
            }
#pragma unroll
            for (int mt = 0; mt < 4; mt++)
#pragma unroll
                for (int nt = 0; nt < 4; nt++) {
                    const int np = nt >> 1, ni = nt & 1;
                    mma16816(acc[mt][nt], aFh[mt], bFh[np][ni], bFh[np][ni + 2]);
                    mma16816(acc[mt][nt], aFh[mt], bFl[np][ni], bFl[np][ni + 2]);
                    mma16816(acc[mt][nt], aFl[mt], bFh[np][ni], bFh[np][ni + 2]);
                }
        }
        __syncthreads();
        if (kt < 23) {
#pragma unroll
            for (int p = 0; p < 4; p++)
#pragma unroll
                for (int it = 0; it < 2; it++) {
                    int r = lr + it * 64;
                    *(uint4*)&smt[p * 5120 + r * 40 + lc8 * 8] = pref[p * 2 + it];
                }
            __syncthreads();
        }
    }

    const int g = lane >> 2;
    const int cb = (lane & 3) * 2;

    if (MODE == 0) {
#pragma unroll
        for (int mt = 0; mt < 4; mt++)
#pragma unroll
            for (int nt = 0; nt < 4; nt++) {
                const size_t col = n0 + wc * 32 + nt * 8 + cb;
                float2 bv = *(const float2*)&bias[col];
                const size_t r0 = m0 + wr * 64 + mt * 16 + g;
                float2 v0 = {acc[mt][nt][0] + bv.x, acc[mt][nt][1] + bv.y};
                float2 v1 = {acc[mt][nt][2] + bv.x, acc[mt][nt][3] + bv.y};
                *(float2*)&out[r0 * ld_out + col]       = v0;
                *(float2*)&out[(r0 + 8) * ld_out + col] = v1;
            }
    } else {
        const int t  = (int)(n0 / D_);          // 128-blocks never cross tensors
        const int nn = (int)(n0 - t * D_);
        __nv_bfloat16* dh = (t == 0) ? g_qh : (t == 1) ? g_kh : g_vh;
        __nv_bfloat16* dl = (t == 0) ? g_ql : (t == 1) ? g_kl : g_vl;
        const float sc = (t == 0) ? 0.125f : 1.0f;
#pragma unroll
        for (int mt = 0; mt < 4; mt++)
#pragma unroll
            for (int nt = 0; nt < 4; nt++) {
                const int colw = nn + wc * 32 + nt * 8 + cb;
                float2 bv = *(const float2*)&bias[n0 + wc * 32 + nt * 8 + cb];
                const size_t r0 = m0 + wr * 64 + mt * 16 + g;
                uint32_t h0, l0, h1, l1;
                split2((acc[mt][nt][0] + bv.x) * sc, (acc[mt][nt][1] + bv.y) * sc, h0, l0);
                split2((acc[mt][nt][2] + bv.x) * sc, (acc[mt][nt][3] + bv.y) * sc, h1, l1);
                *(uint32_t*)&dh[r0 * D_ + colw]       = h0;
                *(uint32_t*)&dl[r0 * D_ + colw]       = l0;
                *(uint32_t*)&dh[(r0 + 8) * D_ + colw] = h1;
                *(uint32_t*)&dl[(r0 + 8) * D_ + colw] = l1;
            }
    }
}

// ------------------- mma.sync bf16x3 causal flash attention -----------------
// CTA: (b, h, 128 q-rows). 8 warps; warp owns 16 rows; kv tiles of 64.
// Dynamic smem: two KV buffers of [Kh|Kl|Vh|Vl], each part 64x72 bf16.
// Q phase (hi 128x72 | lo 128x72) aliases buffer 0+1 region. cp.async pipeline.
#define PART_ 4608                 // elements per part (64*72)
#define BUF_  (4 * PART_)          // elements per KV buffer
__global__ __launch_bounds__(256, 1) void attn_mma_kernel() {
    extern __shared__ __align__(16) char dsm[];
    __nv_bfloat16* sm = (__nv_bfloat16*)dsm;
    const uint32_t sb = smem_u32(sm);

    const int tid = threadIdx.x, wid = tid >> 5, lane = tid & 31;
    const int qt = gridDim.x - 1 - blockIdx.x;
    const int bh = blockIdx.y;
    const int b = bh / H_, h = bh % H_;
    const int q0 = qt * 128;

    // ---- Q tile (pre-scaled, pre-split) -> smem ----
#pragma unroll
    for (int it = 0; it < 8; it++) {
        int idx = tid + it * 256;             // < 2048
        int part = idx >> 10;                 // 0 = hi, 1 = lo
        int w = idx & 1023;
        int r = w >> 3, c8 = w & 7;
        const __nv_bfloat16* src = part ? g_ql : g_qh;
        *(uint4*)&sm[part * 9216 + r * 72 + c8 * 8] =
            *(const uint4*)&src[(size_t)(b * S_ + q0 + r) * D_ + h * 64 + c8 * 8];
    }
    __syncthreads();

    uint32_t aQh[4][4], aQl[4][4];
    {
        const int row = wid * 16 + (lane & 15);
        const int c8 = (lane >> 4) * 8;
#pragma unroll
        for (int kk = 0; kk < 4; kk++) {
            ldsm_x4(aQh[kk], sb + (row * 72 + kk * 16 + c8) * 2);
            ldsm_x4(aQl[kk], sb + (9216 + row * 72 + kk * 16 + c8) * 2);
        }
    }
    __syncthreads();   // Q smem region free; buffers may be written

    float oacc[8][4] = {};
    float mrun[2] = {-1e30f, -1e30f}, lrun[2] = {0.0f, 0.0f};

    const int lrw = lane & 15;
    const int cb8 = (lane >> 4) * 8;
    const int ntiles = 2 * qt + 2;

    // loader lambda (cp.async, 8 x 16B per thread)
    const int lpart = (tid * 8) >> 9;          // constant per-thread mapping below
    auto load_tile = [&](int kt, int bs) {
        const int k0 = kt * 64;
#pragma unroll
        for (int it = 0; it < 8; it++) {
            int idx = tid + it * 256;          // < 2048
            int part = idx >> 9;               // 0 Kh, 1 Kl, 2 Vh, 3 Vl
            int w = idx & 511;
            int row = w >> 3, c8 = w & 7;
            uint32_t dst = sb + (bs * BUF_ + part * PART_ + row * 72 + c8 * 8) * 2;
            const __nv_bfloat16* src;
            if (part < 2) {
                const __nv_bfloat16* base = part ? g_kl : g_kh;
                src = &base[(size_t)(b * S_ + k0 + row) * D_ + h * 64 + c8 * 8];
            } else {
                const __nv_bfloat16* base = (part == 2) ? g_vth : g_vtl;
                src = &base[((size_t)bh * 64 + row) * S_ + k0 + c8 * 8];
            }
            CP_ASYNC16(dst, src);
        }
        CP_COMMIT();
    };
    (void)lpart;

    load_tile(0, 0);

    for (int kt = 0; kt < ntiles; kt++) {
        const int bs = kt & 1;
        if (kt + 1 < ntiles) { load_tile(kt + 1, 1 - bs); CP_WAIT(1); }
        else                 { CP_WAIT(0); }
        __syncthreads();

        const uint32_t kbase = sb + (bs * BUF_) * 2;
        const uint32_t vbase = sb + (bs * BUF_ + 2 * PART_) * 2;

        // ---- S = Q K^T (bf16x3) ----
        float sacc[8][4] = {};
#pragma unroll
        for (int kk = 0; kk < 4; kk++) {
#pragma unroll
            for (int np = 0; np < 4; np++) {
                uint32_t kbh[4], kbl[4];
                ldsm_x4(kbh, kbase + ((np * 16 + lrw) * 72 + kk * 16 + cb8) * 2);
                ldsm_x4(kbl, kbase + (PART_ + (np * 16 + lrw) * 72 + kk * 16 + cb8) * 2);
#pragma unroll
                for (int ni = 0; ni < 2; ni++) {
                    const int nt = np * 2 + ni;
                    mma16816(sacc[nt], aQh[kk], kbh[ni], kbh[ni + 2]);
                    mma16816(sacc[nt], aQh[kk], kbl[ni], kbl[ni + 2]);
                    mma16816(sacc[nt], aQl[kk], kbh[ni], kbh[ni + 2]);
                }
            }
        }

        // ---- causal mask (last two tiles only) ----
        const int k0 = kt * 64;
        if (kt >= 2 * qt) {
#pragma unroll
            for (int nt = 0; nt < 8; nt++)
#pragma unroll
                for (int e = 0; e < 4; e++) {
                    const int row = q0 + wid * 16 + (lane >> 2) + (e >> 1) * 8;
                    const int col = k0 + nt * 8 + (lane & 3) * 2 + (e & 1);
                    if (col > row) sacc[nt][e] = -1e30f;
                }
        }

        // ---- streaming softmax ----
#pragma unroll
        for (int rg = 0; rg < 2; rg++) {
            float mloc = -1e30f;
#pragma unroll
            for (int nt = 0; nt < 8; nt++)
                mloc = fmaxf(mloc, fmaxf(sacc[nt][rg * 2], sacc[nt][rg * 2 + 1]));
            mloc = fmaxf(mloc, __shfl_xor_sync(0xffffffffu, mloc, 1));
            mloc = fmaxf(mloc, __shfl_xor_sync(0xffffffffu, mloc, 2));
            const float mnew = fmaxf(mrun[rg], mloc);
            const float alpha = __expf(mrun[rg] - mnew);
            float lloc = 0.0f;
#pragma unroll
            for (int nt = 0; nt < 8; nt++) {
                sacc[nt][rg * 2]     = __expf(sacc[nt][rg * 2] - mnew);
                sacc[nt][rg * 2 + 1] = __expf(sacc[nt][rg * 2 + 1] - mnew);
                lloc += sacc[nt][rg * 2] + sacc[nt][rg * 2 + 1];
            }
            lloc += __shfl_xor_sync(0xffffffffu, lloc, 1);
            lloc += __shfl_xor_sync(0xffffffffu, lloc, 2);
            lrun[rg] = lrun[rg] * alpha + lloc;
            mrun[rg] = mnew;
#pragma unroll
            for (int dt = 0; dt < 8; dt++) {
                oacc[dt][rg * 2]     *= alpha;
                oacc[dt][rg * 2 + 1] *= alpha;
            }
        }

        // ---- repack P -> A frags (hi/lo) ----
        uint32_t aPh[4][4], aPl[4][4];
#pragma unroll
        for (int k2 = 0; k2 < 4; k2++) {
            split2(sacc[k2 * 2][0],     sacc[k2 * 2][1],     aPh[k2][0], aPl[k2][0]);
            split2(sacc[k2 * 2][2],     sacc[k2 * 2][3],     aPh[k2][1], aPl[k2][1]);
            split2(sacc[k2 * 2 + 1][0], sacc[k2 * 2 + 1][1], aPh[k2][2], aPl[k2][2]);
            split2(sacc[k2 * 2 + 1][2], sacc[k2 * 2 + 1][3], aPh[k2][3], aPl[k2][3]);
        }

        // ---- O += P V (bf16x3) ----
#pragma unroll
        for (int k2 = 0; k2 < 4; k2++) {
#pragma unroll
            for (int dp = 0; dp < 4; dp++) {
                uint32_t vbh[4], vbl[4];
                ldsm_x4(vbh, vbase + ((dp * 16 + lrw) * 72 + k2 * 16 + cb8) * 2);
                ldsm_x4(vbl, vbase + (PART_ + (dp * 16 + lrw) * 72 + k2 * 16 + cb8) * 2);
#pragma unroll
                for (int ni = 0; ni < 2; ni++) {
                    const int dt = dp * 2 + ni;
                    mma16816(oacc[dt], aPh[k2], vbh[ni], vbh[ni + 2]);
                    mma16816(oacc[dt], aPh[k2], vbl[ni], vbl[ni + 2]);
                    mma16816(oacc[dt], aPl[k2], vbh[ni], vbh[ni + 2]);
                }
            }
        }
        __syncthreads();   // all reads of buf bs done before it is refilled
    }

    // ---- epilogue: z = O / l, split bf16 hi/lo ----
#pragma unroll
    for (int rg = 0; rg < 2; rg++) {
        const float inv = 1.0f / lrun[rg];
        const int row = q0 + wid * 16 + (lane >> 2) + rg * 8;
#pragma unroll
        for (int dt = 0; dt < 8; dt++) {
            const size_t o = (size_t)(b * S_ + row) * D_ + h * 64 + dt * 8 + (lane & 3) * 2;
            uint32_t hp, lp;
            split2(oacc[dt][rg * 2] * inv, oacc[dt][rg * 2 + 1] * inv, hp, lp);
            *(uint32_t*)&g_zh[o] = hp;
            *(uint32_t*)&g_zl[o] = lp;
        }
    }
}

// --------------------------------- launch ----------------------------------
extern "C" void kernel_launch(void* const* d_in, const int* in_sizes, int n_in,
                              void* d_out, int out_size) {
    const float* X  = (const float*)d_in[0];
    const float* Wq = (const float*)d_in[1];
    const float* Wk = (const float*)d_in[2];
    const float* Wv = (const float*)d_in[3];
    const float* Wo = (const float*)d_in[4];
    const float* bq = (const float*)d_in[5];
    const float* bk = (const float*)d_in[6];
    const float* bv = (const float*)d_in[7];
    const float* bo = (const float*)d_in[8];
    float* out = (float*)d_out;

    const int attn_smem = 2 * BUF_ * 2;   // 73728 bytes
    static bool attr_set = false;
    if (!attr_set) {
        cudaFuncSetAttribute(attn_mma_kernel,
                             cudaFuncAttributeMaxDynamicSharedMemorySize, attn_smem);
        attr_set = true;
    }

    static __nv_bfloat16 *xh = nullptr, *xl, *zh, *zl, *wth, *wtl, *woh, *wol;
    static float *fb;
    if (!xh) {
        cudaGetSymbolAddress((void**)&xh,  g_xh);
        cudaGetSymbolAddress((void**)&xl,  g_xl);
        cudaGetSymbolAddress((void**)&zh,  g_zh);
        cudaGetSymbolAddress((void**)&zl,  g_zl);
        cudaGetSymbolAddress((void**)&wth, g_wth);
        cudaGetSymbolAddress((void**)&wtl, g_wtl);
        cudaGetSymbolAddress((void**)&woh, g_woh);
        cudaGetSymbolAddress((void**)&wol, g_wol);
        cudaGetSymbolAddress((void**)&fb,  g_fb);
    }

    // 1) conversions
    split_kernel<<<(M_ * D_) / (256 * 8), 256>>>(X, xh, xl, M_ * D_);
    trans_qkv_kernel<<<dim3(D_ / 64, 3 * H_), 256>>>(Wq, Wk, Wv);
    trans_wo_kernel<<<dim3(D_ / 64, D_ / 64), 256>>>(Wo);
    fuse_bias_kernel<<<(NF_ + 255) / 256, 256>>>(bq, bk, bv);

    // 2) fused QKV projection -> split bf16 q/k/v (q pre-scaled)
    gemm_mma_kernel<1><<<dim3(NF_ / 128, M_ / 128), 256>>>(
        xh, xl, wth, wtl, nullptr, 0, fb);

    // 3) V transpose to [bh][dh][s]
    trans_v_kernel<<<dim3(S_ / 64, B_ * H_), 256>>>();

    // 4) causal attention (tensor cores, cp.async pipeline)
    attn_mma_kernel<<<dim3(S_ / 128, B_ * H_), 256, attn_smem>>>();

    // 5) output projection
    gemm_mma_kernel<0><<<dim3(D_ / 128, M_ / 128), 256>>>(
        zh, zl, woh, wol, out, D_, bo);
}

// round 7
// speedup vs baseline: 2.8368x; 1.0227x over previous
#include <cuda_runtime.h>
#include <cuda_bf16.h>
#include <cstdint>

#define B_  4
#define S_  2048
#define D_  768
#define H_  12
#define M_  (B_ * S_)     // 8192
#define NF_ (3 * D_)      // 2304 fused qkv cols

// ------------------------- device scratch (no allocs) -----------------------
__device__ __nv_bfloat16  g_xh [(size_t)M_ * D_];    // residual hi/lo
__device__ __nv_bfloat16  g_xl [(size_t)M_ * D_];
__device__ __nv_bfloat16  g_qh [(size_t)M_ * D_];    // q (pre-scaled) hi/lo
__device__ __nv_bfloat16  g_ql [(size_t)M_ * D_];
__device__ __nv_bfloat16  g_kh [(size_t)M_ * D_];    // k hi/lo
__device__ __nv_bfloat16  g_kl [(size_t)M_ * D_];
__device__ __nv_bfloat16  g_vh [(size_t)M_ * D_];    // v hi/lo (natural)
__device__ __nv_bfloat16  g_vl [(size_t)M_ * D_];
__device__ __nv_bfloat16  g_vth[(size_t)B_ * H_ * 64 * S_];  // v^T [bh][dh][s]
__device__ __nv_bfloat16  g_vtl[(size_t)B_ * H_ * 64 * S_];
__device__ __nv_bfloat16  g_zh [(size_t)M_ * D_];    // attention out hi/lo
__device__ __nv_bfloat16  g_zl [(size_t)M_ * D_];
__device__ __nv_bfloat16  g_wth[(size_t)NF_ * D_];   // W_{q,k,v}^T  [n][d]
__device__ __nv_bfloat16  g_wtl[(size_t)NF_ * D_];
__device__ __nv_bfloat16  g_woh[(size_t)D_ * D_];    // W_O^T [d_out][he]
__device__ __nv_bfloat16  g_wol[(size_t)D_ * D_];
__device__ float          g_fb [NF_];                // fused qkv bias

// ------------------------------ PTX helpers --------------------------------
__device__ __forceinline__ uint32_t smem_u32(const void* p) {
    uint32_t a;
    asm("{ .reg .u64 t; cvta.to.shared.u64 t, %1; cvt.u32.u64 %0, t; }"
        : "=r"(a) : "l"(p));
    return a;
}
__device__ __forceinline__ void ldsm_x4(uint32_t* r, uint32_t addr) {
    asm volatile("ldmatrix.sync.aligned.m8n8.x4.shared.b16 {%0,%1,%2,%3}, [%4];"
                 : "=r"(r[0]), "=r"(r[1]), "=r"(r[2]), "=r"(r[3]) : "r"(addr));
}
__device__ __forceinline__ void mma16816(float* c, const uint32_t* a,
                                         uint32_t b0, uint32_t b1) {
    asm volatile(
        "mma.sync.aligned.m16n8k16.row.col.f32.bf16.bf16.f32 "
        "{%0,%1,%2,%3}, {%4,%5,%6,%7}, {%8,%9}, {%0,%1,%2,%3};"
        : "+f"(c[0]), "+f"(c[1]), "+f"(c[2]), "+f"(c[3])
        : "r"(a[0]), "r"(a[1]), "r"(a[2]), "r"(a[3]), "r"(b0), "r"(b1));
}
__device__ __forceinline__ void split2(float a, float b, uint32_t& hi, uint32_t& lo) {
    __nv_bfloat16 ha = __float2bfloat16(a), hb = __float2bfloat16(b);
    __nv_bfloat16 la = __float2bfloat16(a - __bfloat162float(ha));
    __nv_bfloat16 lb = __float2bfloat16(b - __bfloat162float(hb));
    __nv_bfloat162 hp = {ha, hb}, lp = {la, lb};
    hi = *(uint32_t*)&hp; lo = *(uint32_t*)&lp;
}
#define CP_ASYNC16(dst, src) \
    asm volatile("cp.async.cg.shared.global [%0], [%1], 16;" :: "r"(dst), "l"(src))
#define CP_COMMIT() asm volatile("cp.async.commit_group;" ::: "memory")
#define CP_WAIT(n)  asm volatile("cp.async.wait_group %0;" :: "n"(n) : "memory")

// --------------------------- conversion kernels ----------------------------
__global__ void split_kernel(const float* __restrict__ src,
                             __nv_bfloat16* __restrict__ dh,
                             __nv_bfloat16* __restrict__ dl, int n) {
    int i8 = (blockIdx.x * 256 + threadIdx.x) * 8;
    if (i8 >= n) return;
    float4 v0 = *(const float4*)&src[i8];
    float4 v1 = *(const float4*)&src[i8 + 4];
    float v[8] = {v0.x, v0.y, v0.z, v0.w, v1.x, v1.y, v1.z, v1.w};
    __align__(16) __nv_bfloat16 h[8], l[8];
#pragma unroll
    for (int j = 0; j < 8; j++) {
        h[j] = __float2bfloat16(v[j]);
        l[j] = __float2bfloat16(v[j] - __bfloat162float(h[j]));
    }
    *(uint4*)&dh[i8] = *(uint4*)h;
    *(uint4*)&dl[i8] = *(uint4*)l;
}

__device__ __forceinline__ void trans_tile(const float* src, int src_ld,
                                           __nv_bfloat16* dh, __nv_bfloat16* dl,
                                           int dst_ld, int r0, int c0, int base) {
    __shared__ float ts[64 * 65];
    const int tid = threadIdx.x;
#pragma unroll
    for (int it = 0; it < 16; it++) {
        int flat = tid + it * 256;
        int i = flat >> 6, c = flat & 63;
        ts[c * 65 + i] = src[(size_t)(r0 + i) * src_ld + c0 + c];
    }
    __syncthreads();
#pragma unroll
    for (int it = 0; it < 8; it++) {
        int flat = tid + it * 256;
        int c = flat >> 5, rj = flat & 31;
        uint32_t hp, lp;
        split2(ts[c * 65 + rj * 2], ts[c * 65 + rj * 2 + 1], hp, lp);
        size_t o = (size_t)(base + c0 + c) * dst_ld + r0 + rj * 2;
        *(uint32_t*)&dh[o] = hp;
        *(uint32_t*)&dl[o] = lp;
    }
}

__global__ void trans_qkv_kernel(const float* __restrict__ Wq,
                                 const float* __restrict__ Wk,
                                 const float* __restrict__ Wv,
                                 const float* __restrict__ bq,
                                 const float* __restrict__ bk,
                                 const float* __restrict__ bv) {
    const int by = blockIdx.y;
    const int t = by / H_, h = by % H_;
    // fold bias fuse into block x==0 (64 entries per (t,h))
    if (blockIdx.x == 0 && threadIdx.x < 64) {
        const float* bp = (t == 0) ? bq : (t == 1) ? bk : bv;
        g_fb[t * D_ + h * 64 + threadIdx.x] = bp[h * 64 + threadIdx.x];
    }
    const float* src = ((t == 0) ? Wq : (t == 1) ? Wk : Wv) + (size_t)h * D_ * 64;
    trans_tile(src, 64, g_wth, g_wtl, D_, blockIdx.x * 64, 0, t * D_ + h * 64);
}
__global__ void trans_wo_kernel(const float* __restrict__ Wo) {
    trans_tile(Wo, D_, g_woh, g_wol, D_, blockIdx.x * 64, blockIdx.y * 64, 0);
}

// V transpose: g_vh/g_vl [b][s][h*64+e] -> g_vth/g_vtl [(b*H+h)*64+e][s]
__global__ void trans_v_kernel() {
    __shared__ __nv_bfloat16 th[64 * 72], tl[64 * 72];
    const int s0 = blockIdx.x * 64;
    const int bh = blockIdx.y;
    const int b = bh / H_, h = bh % H_;
    const int tid = threadIdx.x;
#pragma unroll
    for (int it = 0; it < 8; it++) {
        int idx = tid + it * 256;
        int s = idx >> 5, e2 = idx & 31;
        uint32_t vh2 = *(const uint32_t*)&g_vh[(size_t)(b * S_ + s0 + s) * D_ + h * 64 + e2 * 2];
        uint32_t vl2 = *(const uint32_t*)&g_vl[(size_t)(b * S_ + s0 + s) * D_ + h * 64 + e2 * 2];
        __nv_bfloat162 hb = *(__nv_bfloat162*)&vh2;
        __nv_bfloat162 lb = *(__nv_bfloat162*)&vl2;
        th[(e2 * 2 + 0) * 72 + s] = hb.x;
        th[(e2 * 2 + 1) * 72 + s] = hb.y;
        tl[(e2 * 2 + 0) * 72 + s] = lb.x;
        tl[(e2 * 2 + 1) * 72 + s] = lb.y;
    }
    __syncthreads();
#pragma unroll
    for (int it = 0; it < 8; it++) {
        int idx = tid + it * 256;
        int e = idx >> 5, s2 = idx & 31;
        size_t o = ((size_t)bh * 64 + e) * S_ + s0 + s2 * 2;
        *(uint32_t*)&g_vth[o] = *(uint32_t*)&th[e * 72 + s2 * 2];
        *(uint32_t*)&g_vtl[o] = *(uint32_t*)&tl[e * 72 + s2 * 2];
    }
}

// ------------------------ mma.sync bf16x3 GEMM ------------------------------
// cp.async double-buffered, occupancy 2. BK=32, CTA 128x128, 8 warps (2x4).
// Dynamic smem: 2 stages x 4 parts x 128x40 bf16 = 81920 B.
#define GP_   5120                 // elements per part (128*40)
#define GSTG_ (4 * GP_)            // elements per stage
template <int MODE>
__global__ __launch_bounds__(256, 2)
void gemm_mma_kernel(const __nv_bfloat16* __restrict__ Ah,
                     const __nv_bfloat16* __restrict__ Al,
                     const __nv_bfloat16* __restrict__ Bh,
                     const __nv_bfloat16* __restrict__ Bl,
                     float* __restrict__ out, int ld_out,
                     const float* __restrict__ bias) {
    extern __shared__ __align__(16) char gsm[];
    const uint32_t sb = smem_u32(gsm);

    const int tid  = threadIdx.x;
    const int wid  = tid >> 5;
    const int lane = tid & 31;
    const int wr   = wid >> 2;
    const int wc   = wid & 3;
    const size_t m0 = blockIdx.y * 128;
    const size_t n0 = blockIdx.x * 128;

    const __nv_bfloat16* srcs[4] = {Ah, Al, Bh, Bl};
    const size_t rbase[4] = {m0, m0, n0, n0};

    // loader: 2048 16B-chunks per stage; 8 per thread.
    // idx = tid + it*256; part = idx>>9; w = idx&511; row = w>>2; c8 = w&3.
    auto load_st = [&](int kt, int st) {
        const int k0 = kt * 32;
#pragma unroll
        for (int it = 0; it < 8; it++) {
            int idx = tid + it * 256;
            int part = idx >> 9;
            int w = idx & 511;
            int row = w >> 2, c8 = w & 3;
            uint32_t dst = sb + (st * GSTG_ + part * GP_ + row * 40 + c8 * 8) * 2;
            const __nv_bfloat16* src =
                &srcs[part][(rbase[part] + row) * D_ + k0 + c8 * 8];
            CP_ASYNC16(dst, src);
        }
        CP_COMMIT();
    };

    float acc[4][4][4] = {};

    const int lrow = lane & 15;
    const int lcol = (lane >> 4) * 8;

    load_st(0, 0);

    for (int kt = 0; kt < 24; kt++) {
        const int st = kt & 1;
        if (kt < 23) { load_st(kt + 1, 1 - st); CP_WAIT(1); }
        else         { CP_WAIT(0); }
        __syncthreads();

        const uint32_t s0 = sb + (st * GSTG_) * 2;
#pragma unroll
        for (int ks = 0; ks < 2; ks++) {
            const int kb = ks * 16;
            uint32_t aFh[4][4], aFl[4][4];
#pragma unroll
            for (int mt = 0; mt < 4; mt++) {
                int row = wr * 64 + mt * 16 + lrow;
                ldsm_x4(aFh[mt], s0 + (0 * GP_ + row * 40 + kb + lcol) * 2);
                ldsm_x4(aFl[mt], s0 + (1 * GP_ + row * 40 + kb + lcol) * 2);
            }
#pragma unroll
            for (int np = 0; np < 2; np++) {
                uint32_t bFh[4], bFl[4];
                int row = wc * 32 + np * 16 + lrow;
                ldsm_x4(bFh, s0 + (2 * GP_ + row * 40 + kb + lcol) * 2);
                ldsm_x4(bFl, s0 + (3 * GP_ + row * 40 + kb + lcol) * 2);
#pragma unroll
                for (int mt = 0; mt < 4; mt++)
#pragma unroll
                    for (int ni = 0; ni < 2; ni++) {
                        const int nt = np * 2 + ni;
                        mma16816(acc[mt][nt], aFh[mt], bFh[ni], bFh[ni + 2]);
                        mma16816(acc[mt][nt], aFh[mt], bFl[ni], bFl[ni + 2]);
                        mma16816(acc[mt][nt], aFl[mt], bFh[ni], bFh[ni + 2]);
                    }
            }
        }
        __syncthreads();
    }

    const int g = lane >> 2;
    const int cb = (lane & 3) * 2;

    if (MODE == 0) {
#pragma unroll
        for (int mt = 0; mt < 4; mt++)
#pragma unroll
            for (int nt = 0; nt < 4; nt++) {
                const size_t col = n0 + wc * 32 + nt * 8 + cb;
                float2 bv = *(const float2*)&bias[col];
                const size_t r0 = m0 + wr * 64 + mt * 16 + g;
                float2 v0 = {acc[mt][nt][0] + bv.x, acc[mt][nt][1] + bv.y};
                float2 v1 = {acc[mt][nt][2] + bv.x, acc[mt][nt][3] + bv.y};
                *(float2*)&out[r0 * ld_out + col]       = v0;
                *(float2*)&out[(r0 + 8) * ld_out + col] = v1;
            }
    } else {
        const int t  = (int)(n0 / D_);          // 128-blocks never cross tensors
        const int nn = (int)(n0 - t * D_);
        __nv_bfloat16* dh = (t == 0) ? g_qh : (t == 1) ? g_kh : g_vh;
        __nv_bfloat16* dl = (t == 0) ? g_ql : (t == 1) ? g_kl : g_vl;
        const float sc = (t == 0) ? 0.125f : 1.0f;
#pragma unroll
        for (int mt = 0; mt < 4; mt++)
#pragma unroll
            for (int nt = 0; nt < 4; nt++) {
                const int colw = nn + wc * 32 + nt * 8 + cb;
                float2 bv = *(const float2*)&bias[n0 + wc * 32 + nt * 8 + cb];
                const size_t r0 = m0 + wr * 64 + mt * 16 + g;
                uint32_t h0, l0, h1, l1;
                split2((acc[mt][nt][0] + bv.x) * sc, (acc[mt][nt][1] + bv.y) * sc, h0, l0);
                split2((acc[mt][nt][2] + bv.x) * sc, (acc[mt][nt][3] + bv.y) * sc, h1, l1);
                *(uint32_t*)&dh[r0 * D_ + colw]       = h0;
                *(uint32_t*)&dl[r0 * D_ + colw]       = l0;
                *(uint32_t*)&dh[(r0 + 8) * D_ + colw] = h1;
                *(uint32_t*)&dl[(r0 + 8) * D_ + colw] = l1;
            }
    }
}

// ------------------- mma.sync bf16x3 causal flash attention -----------------
#define PART_ 4608                 // elements per part (64*72)
#define BUF_  (4 * PART_)          // elements per KV buffer
__global__ __launch_bounds__(256, 1) void attn_mma_kernel() {
    extern __shared__ __align__(16) char dsm[];
    __nv_bfloat16* sm = (__nv_bfloat16*)dsm;
    const uint32_t sb = smem_u32(sm);

    const int tid = threadIdx.x, wid = tid >> 5, lane = tid & 31;
    const int qt = gridDim.x - 1 - blockIdx.x;
    const int bh = blockIdx.y;
    const int b = bh / H_, h = bh % H_;
    const int q0 = qt * 128;

    // ---- Q tile (pre-scaled, pre-split) -> smem ----
#pragma unroll
    for (int it = 0; it < 8; it++) {
        int idx = tid + it * 256;
        int part = idx >> 10;
        int w = idx & 1023;
        int r = w >> 3, c8 = w & 7;
        const __nv_bfloat16* src = part ? g_ql : g_qh;
        *(uint4*)&sm[part * 9216 + r * 72 + c8 * 8] =
            *(const uint4*)&src[(size_t)(b * S_ + q0 + r) * D_ + h * 64 + c8 * 8];
    }
    __syncthreads();

    uint32_t aQh[4][4], aQl[4][4];
    {
        const int row = wid * 16 + (lane & 15);
        const int c8 = (lane >> 4) * 8;
#pragma unroll
        for (int kk = 0; kk < 4; kk++) {
            ldsm_x4(aQh[kk], sb + (row * 72 + kk * 16 + c8) * 2);
            ldsm_x4(aQl[kk], sb + (9216 + row * 72 + kk * 16 + c8) * 2);
        }
    }
    __syncthreads();

    float oacc[8][4] = {};
    float mrun[2] = {-1e30f, -1e30f}, lrun[2] = {0.0f, 0.0f};

    const int lrw = lane & 15;
    const int cb8 = (lane >> 4) * 8;
    const int ntiles = 2 * qt + 2;

    auto load_tile = [&](int kt, int bs) {
        const int k0 = kt * 64;
#pragma unroll
        for (int it = 0; it < 8; it++) {
            int idx = tid + it * 256;
            int part = idx >> 9;
            int w = idx & 511;
            int row = w >> 3, c8 = w & 7;
            uint32_t dst = sb + (bs * BUF_ + part * PART_ + row * 72 + c8 * 8) * 2;
            const __nv_bfloat16* src;
            if (part < 2) {
                const __nv_bfloat16* base = part ? g_kl : g_kh;
                src = &base[(size_t)(b * S_ + k0 + row) * D_ + h * 64 + c8 * 8];
            } else {
                const __nv_bfloat16* base = (part == 2) ? g_vth : g_vtl;
                src = &base[((size_t)bh * 64 + row) * S_ + k0 + c8 * 8];
            }
            CP_ASYNC16(dst, src);
        }
        CP_COMMIT();
    };

    load_tile(0, 0);

    for (int kt = 0; kt < ntiles; kt++) {
        const int bs = kt & 1;
        if (kt + 1 < ntiles) { load_tile(kt + 1, 1 - bs); CP_WAIT(1); }
        else                 { CP_WAIT(0); }
        __syncthreads();

        const uint32_t kbase = sb + (bs * BUF_) * 2;
        const uint32_t vbase = sb + (bs * BUF_ + 2 * PART_) * 2;

        float sacc[8][4] = {};
#pragma unroll
        for (int kk = 0; kk < 4; kk++) {
#pragma unroll
            for (int np = 0; np < 4; np++) {
                uint32_t kbh[4], kbl[4];
                ldsm_x4(kbh, kbase + ((np * 16 + lrw) * 72 + kk * 16 + cb8) * 2);
                ldsm_x4(kbl, kbase + (PART_ + (np * 16 + lrw) * 72 + kk * 16 + cb8) * 2);
#pragma unroll
                for (int ni = 0; ni < 2; ni++) {
                    const int nt = np * 2 + ni;
                    mma16816(sacc[nt], aQh[kk], kbh[ni], kbh[ni + 2]);
                    mma16816(sacc[nt], aQh[kk], kbl[ni], kbl[ni + 2]);
                    mma16816(sacc[nt], aQl[kk], kbh[ni], kbh[ni + 2]);
                }
            }
        }

        const int k0 = kt * 64;
        if (kt >= 2 * qt) {
#pragma unroll
            for (int nt = 0; nt < 8; nt++)
#pragma unroll
                for (int e = 0; e < 4; e++) {
                    const int row = q0 + wid * 16 + (lane >> 2) + (e >> 1) * 8;
                    const int col = k0 + nt * 8 + (lane & 3) * 2 + (e & 1);
                    if (col > row) sacc[nt][e] = -1e30f;
                }
        }

#pragma unroll
        for (int rg = 0; rg < 2; rg++) {
            float mloc = -1e30f;
#pragma unroll
            for (int nt = 0; nt < 8; nt++)
                mloc = fmaxf(mloc, fmaxf(sacc[nt][rg * 2], sacc[nt][rg * 2 + 1]));
            mloc = fmaxf(mloc, __shfl_xor_sync(0xffffffffu, mloc, 1));
            mloc = fmaxf(mloc, __shfl_xor_sync(0xffffffffu, mloc, 2));
            const float mnew = fmaxf(mrun[rg], mloc);
            const float alpha = __expf(mrun[rg] - mnew);
            float lloc = 0.0f;
#pragma unroll
            for (int nt = 0; nt < 8; nt++) {
                sacc[nt][rg * 2]     = __expf(sacc[nt][rg * 2] - mnew);
                sacc[nt][rg * 2 + 1] = __expf(sacc[nt][rg * 2 + 1] - mnew);
                lloc += sacc[nt][rg * 2] + sacc[nt][rg * 2 + 1];
            }
            lloc += __shfl_xor_sync(0xffffffffu, lloc, 1);
            lloc += __shfl_xor_sync(0xffffffffu, lloc, 2);
            lrun[rg] = lrun[rg] * alpha + lloc;
            mrun[rg] = mnew;
#pragma unroll
            for (int dt = 0; dt < 8; dt++) {
                oacc[dt][rg * 2]     *= alpha;
                oacc[dt][rg * 2 + 1] *= alpha;
            }
        }

        uint32_t aPh[4][4], aPl[4][4];
#pragma unroll
        for (int k2 = 0; k2 < 4; k2++) {
            split2(sacc[k2 * 2][0],     sacc[k2 * 2][1],     aPh[k2][0], aPl[k2][0]);
            split2(sacc[k2 * 2][2],     sacc[k2 * 2][3],     aPh[k2][1], aPl[k2][1]);
            split2(sacc[k2 * 2 + 1][0], sacc[k2 * 2 + 1][1], aPh[k2][2], aPl[k2][2]);
            split2(sacc[k2 * 2 + 1][2], sacc[k2 * 2 + 1][3], aPh[k2][3], aPl[k2][3]);
        }

#pragma unroll
        for (int k2 = 0; k2 < 4; k2++) {
#pragma unroll
            for (int dp = 0; dp < 4; dp++) {
                uint32_t vbh[4], vbl[4];
                ldsm_x4(vbh, vbase + ((dp * 16 + lrw) * 72 + k2 * 16 + cb8) * 2);
                ldsm_x4(vbl, vbase + (PART_ + (dp * 16 + lrw) * 72 + k2 * 16 + cb8) * 2);
#pragma unroll
                for (int ni = 0; ni < 2; ni++) {
                    const int dt = dp * 2 + ni;
                    mma16816(oacc[dt], aPh[k2], vbh[ni], vbh[ni + 2]);
                    mma16816(oacc[dt], aPh[k2], vbl[ni], vbl[ni + 2]);
                    mma16816(oacc[dt], aPl[k2], vbh[ni], vbh[ni + 2]);
                }
            }
        }
        __syncthreads();
    }

#pragma unroll
    for (int rg = 0; rg < 2; rg++) {
        const float inv = 1.0f / lrun[rg];
        const int row = q0 + wid * 16 + (lane >> 2) + rg * 8;
#pragma unroll
        for (int dt = 0; dt < 8; dt++) {
            const size_t o = (size_t)(b * S_ + row) * D_ + h * 64 + dt * 8 + (lane & 3) * 2;
            uint32_t hp, lp;
            split2(oacc[dt][rg * 2] * inv, oacc[dt][rg * 2 + 1] * inv, hp, lp);
            *(uint32_t*)&g_zh[o] = hp;
            *(uint32_t*)&g_zl[o] = lp;
        }
    }
}

// --------------------------------- launch ----------------------------------
extern "C" void kernel_launch(void* const* d_in, const int* in_sizes, int n_in,
                              void* d_out, int out_size) {
    const float* X  = (const float*)d_in[0];
    const float* Wq = (const float*)d_in[1];
    const float* Wk = (const float*)d_in[2];
    const float* Wv = (const float*)d_in[3];
    const float* Wo = (const float*)d_in[4];
    const float* bq = (const float*)d_in[5];
    const float* bk = (const float*)d_in[6];
    const float* bv = (const float*)d_in[7];
    const float* bo = (const float*)d_in[8];
    float* out = (float*)d_out;

    const int attn_smem = 2 * BUF_ * 2;     // 73728 B
    const int gemm_smem = 2 * GSTG_ * 2;    // 81920 B
    static bool attr_set = false;
    if (!attr_set) {
        cudaFuncSetAttribute(attn_mma_kernel,
                             cudaFuncAttributeMaxDynamicSharedMemorySize, attn_smem);
        cudaFuncSetAttribute(gemm_mma_kernel<0>,
                             cudaFuncAttributeMaxDynamicSharedMemorySize, gemm_smem);
        cudaFuncSetAttribute(gemm_mma_kernel<1>,
                             cudaFuncAttributeMaxDynamicSharedMemorySize, gemm_smem);
        attr_set = true;
    }

    static __nv_bfloat16 *xh = nullptr, *xl, *zh, *zl, *wth, *wtl, *woh, *wol;
    static float *fb;
    if (!xh) {
        cudaGetSymbolAddress((void**)&xh,  g_xh);
        cudaGetSymbolAddress((void**)&xl,  g_xl);
        cudaGetSymbolAddress((void**)&zh,  g_zh);
        cudaGetSymbolAddress((void**)&zl,  g_zl);
        cudaGetSymbolAddress((void**)&wth, g_wth);
        cudaGetSymbolAddress((void**)&wtl, g_wtl);
        cudaGetSymbolAddress((void**)&woh, g_woh);
        cudaGetSymbolAddress((void**)&wol, g_wol);
        cudaGetSymbolAddress((void**)&fb,  g_fb);
    }

    // 1) conversions (bias fuse folded into trans_qkv)
    split_kernel<<<(M_ * D_) / (256 * 8), 256>>>(X, xh, xl, M_ * D_);
    trans_qkv_kernel<<<dim3(D_ / 64, 3 * H_), 256>>>(Wq, Wk, Wv, bq, bk, bv);
    trans_wo_kernel<<<dim3(D_ / 64, D_ / 64), 256>>>(Wo);

    // 2) fused QKV projection -> split bf16 q/k/v (q pre-scaled)
    gemm_mma_kernel<1><<<dim3(NF_ / 128, M_ / 128), 256, gemm_smem>>>(
        xh, xl, wth, wtl, nullptr, 0, fb);

    // 3) V transpose to [bh][dh][s]
    trans_v_kernel<<<dim3(S_ / 64, B_ * H_), 256>>>();

    // 4) causal attention (tensor cores, cp.async pipeline)
    attn_mma_kernel<<<dim3(S_ / 128, B_ * H_), 256, attn_smem>>>();

    // 5) output projection
    gemm_mma_kernel<0><<<dim3(D_ / 128, M_ / 128), 256, gemm_smem>>>(
        zh, zl, woh, wol, out, D_, bo);
}